// round 1
// baseline (speedup 1.0000x reference)
#include <cuda_runtime.h>
#include <math.h>

#define CL 32
#define NOBJ 32

struct Params {
  const float *s;
  const float *enc_w, *enc_b;
  const float *self_w0, *self_b0, *self_w1, *self_b1;
  const float *rel_w0, *rel_b0, *rel_w1, *rel_b1, *rel_w2, *rel_b2;
  const float *att_w0, *att_b0, *att_w1, *att_b1, *att_w2, *att_b2;
  const float *aff_w0, *aff_b0, *aff_w1, *aff_b1, *aff_w2, *aff_b2;
  const float *out_w0, *out_b0, *out_w1, *out_b1;
  float *out;
};

// Accumulate acc[0..31] += relu(aP[k] + cT[k][j] + dist*wd[k]) * W1[k][m] over k=0..63
__device__ __forceinline__ void pair_accum(
    const float* __restrict__ aP,    // shared: [64], bias already folded, row i
    const float* __restrict__ cT,    // shared: [64][32] transposed, lane j
    const float* __restrict__ wd,    // shared: [64] dist weight row
    float dist, int j,
    const float* __restrict__ W1,    // global: [64][32] row-major
    float acc[32])
{
  #pragma unroll 4
  for (int k = 0; k < 64; ++k) {
    float v = fmaf(dist, wd[k], aP[k] + cT[k * 32 + j]);
    v = fmaxf(v, 0.0f);
    const float4* wr = reinterpret_cast<const float4*>(W1 + k * 32);
    #pragma unroll
    for (int m = 0; m < 8; ++m) {
      float4 q = __ldg(wr + m);
      acc[4*m+0] = fmaf(v, q.x, acc[4*m+0]);
      acc[4*m+1] = fmaf(v, q.y, acc[4*m+1]);
      acc[4*m+2] = fmaf(v, q.z, acc[4*m+2]);
      acc[4*m+3] = fmaf(v, q.w, acc[4*m+3]);
    }
  }
}

__global__ void __launch_bounds__(256, 2) dynamics_kernel(Params p)
{
  // ---- shared layout (46.3 KB) ----
  __shared__ float s2[NOBJ * CL];        // 4 KB   (cols 0,1 = pos)
  __shared__ float aRp[NOBJ * 64];       // 8 KB   a_rel + rel_b0 (also: ssrc overlay, then t3)
  __shared__ float cRT[64 * NOBJ];       // 8 KB   c_rel transposed (also: t2)
  __shared__ float aAp[NOBJ * 64];       // 8 KB   a_att + att_b0 (also: t1)
  __shared__ float cAT[64 * NOBJ];       // 8 KB   c_att transposed
  __shared__ float sdyn[NOBJ * CL];      // 4 KB   self_dyn, then dyn
  __shared__ float rdyn[NOBJ * CL];      // 4 KB   h1, then rel_dyn
  __shared__ float wRd[64], wAd[64];     // dist-weight rows (rel_w0[64], att_w0[64])
  __shared__ float bR1[CL], bA1[CL], bR2[CL], w2A[CL];
  __shared__ float bA2s;

  const int n    = blockIdx.x;
  const int t    = threadIdx.x;
  const int lane = t & 31;
  const int w    = t >> 5;

  // ---- Phase A: load raw s (overlay in aRp), small weight vectors ----
  float* ssrc = aRp;  // 512 floats, freed before aRp is written
  {
    const float* sp = p.s + (size_t)n * (NOBJ * 16);
    #pragma unroll
    for (int idx = t; idx < NOBJ * 16; idx += 256) ssrc[idx] = sp[idx];
  }
  if (t < 64) { wRd[t] = p.rel_w0[64 * 64 + t]; wAd[t] = p.att_w0[64 * 64 + t]; }
  else if (t < 96) {
    int c = t - 64;
    bR1[c] = p.rel_b1[c]; bA1[c] = p.att_b1[c];
    bR2[c] = p.rel_b2[c]; w2A[c] = p.att_w2[c];
  } else if (t == 96) {
    bA2s = p.att_b2[0];
  }
  __syncthreads();

  // ---- s2 = concat(s[:, :2], (s @ enc_w + enc_b)[:, 2:]) ----
  #pragma unroll
  for (int idx = t; idx < NOBJ * CL; idx += 256) {
    int i = idx >> 5, c = idx & 31;
    float acc = p.enc_b[c];
    #pragma unroll
    for (int k = 0; k < 16; ++k)
      acc = fmaf(ssrc[i * 16 + k], p.enc_w[k * 32 + c], acc);
    s2[idx] = (c < 2) ? ssrc[i * 16 + c] : acc;
  }
  __syncthreads();

  // ---- h1 = relu(s2 @ self_w0 + b0)  (stored in rdyn) ----
  #pragma unroll
  for (int idx = t; idx < NOBJ * CL; idx += 256) {
    int i = idx >> 5, c = idx & 31;
    float acc = p.self_b0[c];
    #pragma unroll
    for (int k = 0; k < 32; ++k)
      acc = fmaf(s2[i * 32 + k], p.self_w0[k * 32 + c], acc);
    rdyn[idx] = fmaxf(acc, 0.0f);
  }
  __syncthreads();

  // ---- self_dyn = h1 @ self_w1 + b1 + h1 ----
  #pragma unroll
  for (int idx = t; idx < NOBJ * CL; idx += 256) {
    int i = idx >> 5, c = idx & 31;
    float acc = p.self_b1[c] + rdyn[idx];
    #pragma unroll
    for (int k = 0; k < 32; ++k)
      acc = fmaf(rdyn[i * 32 + k], p.self_w1[k * 32 + c], acc);
    sdyn[idx] = acc;
  }
  __syncthreads();

  // ---- pair projections: a_rel/c_rel, a_att/c_att (c stored transposed) ----
  #pragma unroll
  for (int idx = t; idx < NOBJ * 64; idx += 256) {
    int i = idx >> 6, k = idx & 63;
    float aR = 0.f, cR = 0.f, aA = 0.f, cA = 0.f;
    #pragma unroll
    for (int c = 0; c < 32; ++c) {
      float sv = s2[i * 32 + c];
      aR = fmaf(sv, p.rel_w0[c * 64 + k],        aR);
      cR = fmaf(sv, p.rel_w0[(32 + c) * 64 + k], cR);
      aA = fmaf(sv, p.att_w0[c * 64 + k],        aA);
      cA = fmaf(sv, p.att_w0[(32 + c) * 64 + k], cA);
    }
    aRp[idx]          = aR + p.rel_b0[k];
    cRT[k * 32 + i]   = cR;
    aAp[idx]          = aA + p.att_b0[k];
    cAT[k * 32 + i]   = cA;
  }
  __syncthreads();

  // ---- Phase C: pairwise. warp handles rows i = w*4 + it, lane = j ----
  const int j = lane;
  #pragma unroll 1
  for (int it = 0; it < 4; ++it) {
    const int i = w * 4 + it;

    float px = s2[i * 32 + 0], py = s2[i * 32 + 1];
    float qx = s2[j * 32 + 0], qy = s2[j * 32 + 1];
    float dx = px - qx, dy = py - qy;
    float dist = fmaf(dx, dx, dy * dy);

    // attention branch -> scalar att
    float acc[32];
    #pragma unroll
    for (int m = 0; m < 32; ++m) acc[m] = bA1[m];
    pair_accum(aAp + i * 64, cAT, wAd, dist, j, p.att_w1, acc);
    float attlog = bA2s;
    #pragma unroll
    for (int m = 0; m < 32; ++m)
      attlog = fmaf(fmaxf(acc[m], 0.0f), w2A[m], attlog);
    float attv = expf(attlog);

    // rel branch -> rel2 (relu'd), rel_f
    float r2[32];
    #pragma unroll
    for (int m = 0; m < 32; ++m) r2[m] = bR1[m];
    pair_accum(aRp + i * 64, cRT, wRd, dist, j, p.rel_w1, r2);
    #pragma unroll
    for (int m = 0; m < 32; ++m) r2[m] = fmaxf(r2[m], 0.0f);

    float rf[32];
    #pragma unroll
    for (int m = 0; m < 32; ++m) rf[m] = bR2[m] + r2[m];
    #pragma unroll
    for (int k = 0; k < 32; ++k) {
      float v = r2[k];
      const float4* wr = reinterpret_cast<const float4*>(p.rel_w2 + k * 32);
      #pragma unroll
      for (int m = 0; m < 8; ++m) {
        float4 q = __ldg(wr + m);
        rf[4*m+0] = fmaf(v, q.x, rf[4*m+0]);
        rf[4*m+1] = fmaf(v, q.y, rf[4*m+1]);
        rf[4*m+2] = fmaf(v, q.z, rf[4*m+2]);
        rf[4*m+3] = fmaf(v, q.w, rf[4*m+3]);
      }
    }

    float scale = (i == j) ? 0.0f : attv;

    // reduce over j (lanes): rel_dyn[i][c] = sum_j rf[c]*scale
    float myout = 0.0f;
    #pragma unroll
    for (int c = 0; c < 32; ++c) {
      float v = rf[c] * scale;
      v += __shfl_xor_sync(0xffffffffu, v, 16);
      v += __shfl_xor_sync(0xffffffffu, v, 8);
      v += __shfl_xor_sync(0xffffffffu, v, 4);
      v += __shfl_xor_sync(0xffffffffu, v, 2);
      v += __shfl_xor_sync(0xffffffffu, v, 1);
      if (lane == c) myout = v;
    }
    rdyn[i * 32 + lane] = myout;
  }
  __syncthreads();

  // ---- Phase D: per-object tail ----
  // dyn = self_dyn + rel_dyn (into sdyn)
  #pragma unroll
  for (int idx = t; idx < NOBJ * CL; idx += 256) sdyn[idx] += rdyn[idx];
  __syncthreads();

  float* t1 = aAp;  // reuse
  float* t2 = cAT;
  float* t3 = aRp;

  // aff1 = tanh(dyn @ aff_w0 + b)
  #pragma unroll
  for (int idx = t; idx < NOBJ * CL; idx += 256) {
    int i = idx >> 5, c = idx & 31;
    float acc2 = p.aff_b0[c];
    #pragma unroll
    for (int k = 0; k < 32; ++k)
      acc2 = fmaf(sdyn[i * 32 + k], p.aff_w0[k * 32 + c], acc2);
    t1[idx] = tanhf(acc2);
  }
  __syncthreads();

  // aff2 = tanh(aff1 @ aff_w1 + b) + aff1
  #pragma unroll
  for (int idx = t; idx < NOBJ * CL; idx += 256) {
    int i = idx >> 5, c = idx & 31;
    float acc2 = p.aff_b1[c];
    #pragma unroll
    for (int k = 0; k < 32; ++k)
      acc2 = fmaf(t1[i * 32 + k], p.aff_w1[k * 32 + c], acc2);
    t2[idx] = tanhf(acc2) + t1[idx];
  }
  __syncthreads();

  // aff3 = aff2 @ aff_w2 + b
  #pragma unroll
  for (int idx = t; idx < NOBJ * CL; idx += 256) {
    int i = idx >> 5, c = idx & 31;
    float acc2 = p.aff_b2[c];
    #pragma unroll
    for (int k = 0; k < 32; ++k)
      acc2 = fmaf(t2[i * 32 + k], p.aff_w2[k * 32 + c], acc2);
    t3[idx] = acc2;
  }
  __syncthreads();

  // o1 = tanh([aff3, s2] @ out_w0 + b)
  #pragma unroll
  for (int idx = t; idx < NOBJ * CL; idx += 256) {
    int i = idx >> 5, c = idx & 31;
    float acc2 = p.out_b0[c];
    #pragma unroll
    for (int k = 0; k < 32; ++k)
      acc2 = fmaf(t3[i * 32 + k], p.out_w0[k * 32 + c], acc2);
    #pragma unroll
    for (int k = 0; k < 32; ++k)
      acc2 = fmaf(s2[i * 32 + k], p.out_w0[(32 + k) * 32 + c], acc2);
    t1[idx] = tanhf(acc2);
  }
  __syncthreads();

  // result = o1 @ out_w1 + b + o1
  float* og = p.out + (size_t)n * (NOBJ * CL);
  #pragma unroll
  for (int idx = t; idx < NOBJ * CL; idx += 256) {
    int i = idx >> 5, c = idx & 31;
    float acc2 = p.out_b1[c] + t1[idx];
    #pragma unroll
    for (int k = 0; k < 32; ++k)
      acc2 = fmaf(t1[i * 32 + k], p.out_w1[k * 32 + c], acc2);
    og[idx] = acc2;
  }
}

extern "C" void kernel_launch(void* const* d_in, const int* in_sizes, int n_in,
                              void* d_out, int out_size)
{
  Params p;
  p.s       = (const float*)d_in[0];
  p.enc_w   = (const float*)d_in[1];  p.enc_b   = (const float*)d_in[2];
  p.self_w0 = (const float*)d_in[3];  p.self_b0 = (const float*)d_in[4];
  p.self_w1 = (const float*)d_in[5];  p.self_b1 = (const float*)d_in[6];
  p.rel_w0  = (const float*)d_in[7];  p.rel_b0  = (const float*)d_in[8];
  p.rel_w1  = (const float*)d_in[9];  p.rel_b1  = (const float*)d_in[10];
  p.rel_w2  = (const float*)d_in[11]; p.rel_b2  = (const float*)d_in[12];
  p.att_w0  = (const float*)d_in[13]; p.att_b0  = (const float*)d_in[14];
  p.att_w1  = (const float*)d_in[15]; p.att_b1  = (const float*)d_in[16];
  p.att_w2  = (const float*)d_in[17]; p.att_b2  = (const float*)d_in[18];
  p.aff_w0  = (const float*)d_in[19]; p.aff_b0  = (const float*)d_in[20];
  p.aff_w1  = (const float*)d_in[21]; p.aff_b1  = (const float*)d_in[22];
  p.aff_w2  = (const float*)d_in[23]; p.aff_b2  = (const float*)d_in[24];
  p.out_w0  = (const float*)d_in[25]; p.out_b0  = (const float*)d_in[26];
  p.out_w1  = (const float*)d_in[27]; p.out_b1  = (const float*)d_in[28];
  p.out     = (float*)d_out;

  int N = in_sizes[0] / (NOBJ * (CL / 2));
  dynamics_kernel<<<N, 256>>>(p);
}

// round 2
// speedup vs baseline: 2.2520x; 2.2520x over previous
#include <cuda_runtime.h>
#include <math.h>

#define CL 32
#define NOBJ 32

struct Params {
  const float *s;
  const float *enc_w, *enc_b;
  const float *self_w0, *self_b0, *self_w1, *self_b1;
  const float *rel_w0, *rel_b0, *rel_w1, *rel_b1, *rel_w2, *rel_b2;
  const float *att_w0, *att_b0, *att_w1, *att_b1, *att_w2, *att_b2;
  const float *aff_w0, *aff_b0, *aff_w1, *aff_b1, *aff_w2, *aff_b2;
  const float *out_w0, *out_b0, *out_w1, *out_b1;
  float *out;
};

// Transpose-reduce: lane j holds v[c] for c=0..31; returns to lane m the value
// sum_j v[m]. 31 shuffles total (vs 160 for per-channel butterfly).
__device__ __forceinline__ float reduce_t32(float v[32], int lane) {
  float a16[16];
  #pragma unroll
  for (int t = 0; t < 16; ++t) {
    bool hi = (lane & 16) != 0;
    float g = hi ? v[t] : v[t + 16];
    float k = hi ? v[t + 16] : v[t];
    a16[t] = k + __shfl_xor_sync(0xffffffffu, g, 16);
  }
  float a8[8];
  #pragma unroll
  for (int t = 0; t < 8; ++t) {
    bool hi = (lane & 8) != 0;
    float g = hi ? a16[t] : a16[t + 8];
    float k = hi ? a16[t + 8] : a16[t];
    a8[t] = k + __shfl_xor_sync(0xffffffffu, g, 8);
  }
  float a4[4];
  #pragma unroll
  for (int t = 0; t < 4; ++t) {
    bool hi = (lane & 4) != 0;
    float g = hi ? a4[0] : a4[0]; // placeholder (overwritten below)
    (void)g;
    float gg = hi ? a8[t] : a8[t + 4];
    float kk = hi ? a8[t + 4] : a8[t];
    a4[t] = kk + __shfl_xor_sync(0xffffffffu, gg, 4);
  }
  float a2[2];
  #pragma unroll
  for (int t = 0; t < 2; ++t) {
    bool hi = (lane & 2) != 0;
    float gg = hi ? a4[t] : a4[t + 2];
    float kk = hi ? a4[t + 2] : a4[t];
    a2[t] = kk + __shfl_xor_sync(0xffffffffu, gg, 2);
  }
  bool hi = (lane & 1) != 0;
  float gg = hi ? a2[0] : a2[1];
  float kk = hi ? a2[1] : a2[0];
  return kk + __shfl_xor_sync(0xffffffffu, gg, 1);
}

// Core pair accumulation for TWO i-rows sharing one weight stream.
// acc{1,2}[m] += relu(a{1,2}[k] + cT[k][j] + dist{1,2}*wd[k]) * W1[k][m], k=0..63
#define PAIR_STEP(COMP, KOFF)                                                  \
  {                                                                            \
    float v1 = fmaxf(fmaf(dist1, wd.COMP, a1.COMP + ct.COMP), 0.0f);           \
    float v2 = fmaxf(fmaf(dist2, wd.COMP, a2.COMP + ct.COMP), 0.0f);           \
    const float4* wr = wb4 + (k4 * 4 + KOFF) * 8;                              \
    _Pragma("unroll")                                                          \
    for (int m4 = 0; m4 < 8; ++m4) {                                           \
      float4 wv = wr[m4];                                                      \
      acc1[4*m4+0] = fmaf(v1, wv.x, acc1[4*m4+0]);                             \
      acc2[4*m4+0] = fmaf(v2, wv.x, acc2[4*m4+0]);                             \
      acc1[4*m4+1] = fmaf(v1, wv.y, acc1[4*m4+1]);                             \
      acc2[4*m4+1] = fmaf(v2, wv.y, acc2[4*m4+1]);                             \
      acc1[4*m4+2] = fmaf(v1, wv.z, acc1[4*m4+2]);                             \
      acc2[4*m4+2] = fmaf(v2, wv.z, acc2[4*m4+2]);                             \
      acc1[4*m4+3] = fmaf(v1, wv.w, acc1[4*m4+3]);                             \
      acc2[4*m4+3] = fmaf(v2, wv.w, acc2[4*m4+3]);                             \
    }                                                                          \
  }

__device__ __forceinline__ void pair_accum2(
    const float* __restrict__ proj_a, const float4* __restrict__ c4,
    const float4* __restrict__ wd4v, const float4* __restrict__ wb4,
    const float* __restrict__ bias1,
    float dist1, float dist2, int i1, int i2, int j,
    float acc1[32], float acc2[32])
{
  #pragma unroll
  for (int m = 0; m < 32; ++m) { float b = bias1[m]; acc1[m] = b; acc2[m] = b; }
  const float4* a1p = reinterpret_cast<const float4*>(proj_a + i1 * 64);
  const float4* a2p = reinterpret_cast<const float4*>(proj_a + i2 * 64);
  #pragma unroll
  for (int k4 = 0; k4 < 16; ++k4) {
    float4 ct = c4[k4 * 33 + j];
    float4 a1 = a1p[k4];
    float4 a2 = a2p[k4];
    float4 wd = wd4v[k4];
    PAIR_STEP(x, 0)
    PAIR_STEP(y, 1)
    PAIR_STEP(z, 2)
    PAIR_STEP(w, 3)
  }
}

__global__ void __launch_bounds__(256, 2) dynamics_kernel(Params p)
{
  // ---- shared (~42 KB) ----
  __shared__ float s2[NOBJ * CL];          // 4 KB
  __shared__ float proj_a[NOBJ * 64];      // 8 KB  a+bias (att then rel); later t1
  __shared__ float proj_c[16 * 33 * 4];    // 8.25KB cT in float4-group layout; later t2
  __shared__ float wbuf[2048];             // 8 KB  W1 att / W1 rel / [W2 | t3]
  __shared__ float sdyn[NOBJ * CL];        // 4 KB  self_dyn -> dyn
  __shared__ float Ssm[NOBJ * CL];         // 4 KB  h1 scratch, then S matrix
  __shared__ float attv[NOBJ * CL];        // 4 KB  ssrc scratch, then att values
  __shared__ float4 wd4[16];               // dist-weight row (per pass)
  __shared__ float miscA[32], miscB[32], miscC[32];
  __shared__ float Avec[32];
  __shared__ float bA2s;

  const int n    = blockIdx.x;
  const int t    = threadIdx.x;
  const int lane = t & 31;
  const int w    = t >> 5;

  // ---- Phase A: stage raw s (overlay in attv) ----
  {
    float* ssrc = attv;
    const float* sp = p.s + (size_t)n * (NOBJ * 16);
    #pragma unroll
    for (int idx = t; idx < NOBJ * 16; idx += 256) ssrc[idx] = sp[idx];
  }
  __syncthreads();

  // s2 = concat(s[:, :2], (s @ enc_w + enc_b)[:, 2:])
  {
    const float* ssrc = attv;
    #pragma unroll
    for (int idx = t; idx < NOBJ * CL; idx += 256) {
      int i = idx >> 5, c = idx & 31;
      float acc = __ldg(&p.enc_b[c]);
      #pragma unroll
      for (int k = 0; k < 16; ++k)
        acc = fmaf(ssrc[i * 16 + k], __ldg(&p.enc_w[k * 32 + c]), acc);
      s2[idx] = (c < 2) ? ssrc[i * 16 + c] : acc;
    }
  }
  __syncthreads();

  // ---- Phase B: self branch ----
  #pragma unroll
  for (int idx = t; idx < NOBJ * CL; idx += 256) {
    int i = idx >> 5, c = idx & 31;
    float acc = __ldg(&p.self_b0[c]);
    #pragma unroll
    for (int k = 0; k < 32; ++k)
      acc = fmaf(s2[i * 32 + k], __ldg(&p.self_w0[k * 32 + c]), acc);
    Ssm[idx] = fmaxf(acc, 0.0f);   // h1
  }
  __syncthreads();
  #pragma unroll
  for (int idx = t; idx < NOBJ * CL; idx += 256) {
    int i = idx >> 5, c = idx & 31;
    float acc = __ldg(&p.self_b1[c]) + Ssm[idx];
    #pragma unroll
    for (int k = 0; k < 32; ++k)
      acc = fmaf(Ssm[i * 32 + k], __ldg(&p.self_w1[k * 32 + c]), acc);
    sdyn[idx] = acc;
  }
  __syncthreads();

  const int j = lane;
  const float qx = s2[j * 32 + 0], qy = s2[j * 32 + 1];

  // ============ ATT PASS ============
  // setup: W1 -> wbuf, projections, wd row, misc
  {
    const float4* src = reinterpret_cast<const float4*>(p.att_w1);
    float4* dst = reinterpret_cast<float4*>(wbuf);
    #pragma unroll
    for (int idx = t; idx < 512; idx += 256) dst[idx] = __ldg(src + idx);
  }
  if (t < 64) reinterpret_cast<float*>(wd4)[t] = __ldg(&p.att_w0[64 * 64 + t]);
  else if (t < 96) { int c = t - 64; miscA[c] = __ldg(&p.att_b1[c]); miscB[c] = __ldg(&p.att_w2[c]); }
  else if (t == 96) bA2s = __ldg(&p.att_b2[0]);
  #pragma unroll
  for (int idx = t; idx < NOBJ * 64; idx += 256) {
    int i = idx >> 6, k = idx & 63;
    float a = 0.f, c = 0.f;
    #pragma unroll
    for (int cc = 0; cc < 32; ++cc) {
      float sv = s2[i * 32 + cc];
      a = fmaf(sv, __ldg(&p.att_w0[cc * 64 + k]), a);
      c = fmaf(sv, __ldg(&p.att_w0[(32 + cc) * 64 + k]), c);
    }
    proj_a[i * 64 + k] = a + __ldg(&p.att_b0[k]);
    proj_c[((k >> 2) * 33 + i) * 4 + (k & 3)] = c;
  }
  __syncthreads();

  #pragma unroll 1
  for (int it = 0; it < 2; ++it) {
    const int i1 = w * 4 + it * 2;
    const int i2 = i1 + 1;
    float dx1 = s2[i1 * 32 + 0] - qx, dy1 = s2[i1 * 32 + 1] - qy;
    float dx2 = s2[i2 * 32 + 0] - qx, dy2 = s2[i2 * 32 + 1] - qy;
    float dist1 = fmaf(dx1, dx1, dy1 * dy1);
    float dist2 = fmaf(dx2, dx2, dy2 * dy2);

    float acc1[32], acc2[32];
    pair_accum2(proj_a, reinterpret_cast<const float4*>(proj_c), wd4,
                reinterpret_cast<const float4*>(wbuf), miscA,
                dist1, dist2, i1, i2, j, acc1, acc2);

    float l1 = bA2s, l2 = bA2s;
    #pragma unroll
    for (int m = 0; m < 32; ++m) {
      float wm = miscB[m];
      l1 = fmaf(fmaxf(acc1[m], 0.0f), wm, l1);
      l2 = fmaf(fmaxf(acc2[m], 0.0f), wm, l2);
    }
    attv[i1 * 32 + j] = (j == i1) ? 0.0f : expf(l1);
    attv[i2 * 32 + j] = (j == i2) ? 0.0f : expf(l2);
  }
  __syncthreads();

  // ============ REL PASS ============
  {
    const float4* src = reinterpret_cast<const float4*>(p.rel_w1);
    float4* dst = reinterpret_cast<float4*>(wbuf);
    #pragma unroll
    for (int idx = t; idx < 512; idx += 256) dst[idx] = __ldg(src + idx);
  }
  if (t < 64) reinterpret_cast<float*>(wd4)[t] = __ldg(&p.rel_w0[64 * 64 + t]);
  else if (t < 96) { int c = t - 64; miscA[c] = __ldg(&p.rel_b1[c]); }
  #pragma unroll
  for (int idx = t; idx < NOBJ * 64; idx += 256) {
    int i = idx >> 6, k = idx & 63;
    float a = 0.f, c = 0.f;
    #pragma unroll
    for (int cc = 0; cc < 32; ++cc) {
      float sv = s2[i * 32 + cc];
      a = fmaf(sv, __ldg(&p.rel_w0[cc * 64 + k]), a);
      c = fmaf(sv, __ldg(&p.rel_w0[(32 + cc) * 64 + k]), c);
    }
    proj_a[i * 64 + k] = a + __ldg(&p.rel_b0[k]);
    proj_c[((k >> 2) * 33 + i) * 4 + (k & 3)] = c;
  }
  __syncthreads();

  #pragma unroll 1
  for (int it = 0; it < 2; ++it) {
    const int i1 = w * 4 + it * 2;
    const int i2 = i1 + 1;
    float dx1 = s2[i1 * 32 + 0] - qx, dy1 = s2[i1 * 32 + 1] - qy;
    float dx2 = s2[i2 * 32 + 0] - qx, dy2 = s2[i2 * 32 + 1] - qy;
    float dist1 = fmaf(dx1, dx1, dy1 * dy1);
    float dist2 = fmaf(dx2, dx2, dy2 * dy2);

    float acc1[32], acc2[32];
    pair_accum2(proj_a, reinterpret_cast<const float4*>(proj_c), wd4,
                reinterpret_cast<const float4*>(wbuf), miscA,
                dist1, dist2, i1, i2, j, acc1, acc2);

    // S[i,m] = sum_j att * relu(rel2_pre);  A[i] = sum_j att
    float at1 = attv[i1 * 32 + j];
    float at2 = attv[i2 * 32 + j];
    #pragma unroll
    for (int m = 0; m < 32; ++m) acc1[m] = at1 * fmaxf(acc1[m], 0.0f);
    #pragma unroll
    for (int m = 0; m < 32; ++m) acc2[m] = at2 * fmaxf(acc2[m], 0.0f);

    float S1 = reduce_t32(acc1, lane);
    float S2 = reduce_t32(acc2, lane);
    float as1 = at1, as2 = at2;
    #pragma unroll
    for (int o = 16; o >= 1; o >>= 1) {
      as1 += __shfl_xor_sync(0xffffffffu, as1, o);
      as2 += __shfl_xor_sync(0xffffffffu, as2, o);
    }
    Ssm[i1 * 32 + lane] = S1;
    Ssm[i2 * 32 + lane] = S2;
    if (lane == 0) { Avec[i1] = as1; Avec[i2] = as2; }
  }
  __syncthreads();

  // ---- load W2 + b2 ----
  {
    const float4* src = reinterpret_cast<const float4*>(p.rel_w2);
    float4* dst = reinterpret_cast<float4*>(wbuf);
    #pragma unroll
    for (int idx = t; idx < 256; idx += 256) dst[idx] = __ldg(src + idx);
  }
  if (t >= 64 && t < 96) miscC[t - 64] = __ldg(&p.rel_b2[t - 64]);
  __syncthreads();

  // ---- dyn = self_dyn + S@W2 + A*b2 + S ----
  #pragma unroll
  for (int idx = t; idx < NOBJ * CL; idx += 256) {
    int i = idx >> 5, m = idx & 31;
    float acc = sdyn[idx] + Ssm[idx] + Avec[i] * miscC[m];
    #pragma unroll
    for (int k = 0; k < 32; ++k)
      acc = fmaf(Ssm[i * 32 + k], wbuf[k * 32 + m], acc);
    sdyn[idx] = acc;
  }
  __syncthreads();

  // ---- tail: aff / out chain ----
  float* t1 = proj_a;
  float* t2 = proj_c;        // >=1024 floats available
  float* t3 = wbuf + 1024;

  #pragma unroll
  for (int idx = t; idx < NOBJ * CL; idx += 256) {
    int i = idx >> 5, c = idx & 31;
    float acc = __ldg(&p.aff_b0[c]);
    #pragma unroll
    for (int k = 0; k < 32; ++k)
      acc = fmaf(sdyn[i * 32 + k], __ldg(&p.aff_w0[k * 32 + c]), acc);
    t1[idx] = tanhf(acc);
  }
  __syncthreads();

  #pragma unroll
  for (int idx = t; idx < NOBJ * CL; idx += 256) {
    int i = idx >> 5, c = idx & 31;
    float acc = __ldg(&p.aff_b1[c]);
    #pragma unroll
    for (int k = 0; k < 32; ++k)
      acc = fmaf(t1[i * 32 + k], __ldg(&p.aff_w1[k * 32 + c]), acc);
    t2[idx] = tanhf(acc) + t1[idx];
  }
  __syncthreads();

  #pragma unroll
  for (int idx = t; idx < NOBJ * CL; idx += 256) {
    int i = idx >> 5, c = idx & 31;
    float acc = __ldg(&p.aff_b2[c]);
    #pragma unroll
    for (int k = 0; k < 32; ++k)
      acc = fmaf(t2[i * 32 + k], __ldg(&p.aff_w2[k * 32 + c]), acc);
    t3[idx] = acc;
  }
  __syncthreads();

  #pragma unroll
  for (int idx = t; idx < NOBJ * CL; idx += 256) {
    int i = idx >> 5, c = idx & 31;
    float acc = __ldg(&p.out_b0[c]);
    #pragma unroll
    for (int k = 0; k < 32; ++k)
      acc = fmaf(t3[i * 32 + k], __ldg(&p.out_w0[k * 32 + c]), acc);
    #pragma unroll
    for (int k = 0; k < 32; ++k)
      acc = fmaf(s2[i * 32 + k], __ldg(&p.out_w0[(32 + k) * 32 + c]), acc);
    t1[idx] = tanhf(acc);
  }
  __syncthreads();

  float* og = p.out + (size_t)n * (NOBJ * CL);
  #pragma unroll
  for (int idx = t; idx < NOBJ * CL; idx += 256) {
    int i = idx >> 5, c = idx & 31;
    float acc = __ldg(&p.out_b1[c]) + t1[idx];
    #pragma unroll
    for (int k = 0; k < 32; ++k)
      acc = fmaf(t1[i * 32 + k], __ldg(&p.out_w1[k * 32 + c]), acc);
    og[idx] = acc;
  }
}

extern "C" void kernel_launch(void* const* d_in, const int* in_sizes, int n_in,
                              void* d_out, int out_size)
{
  Params p;
  p.s       = (const float*)d_in[0];
  p.enc_w   = (const float*)d_in[1];  p.enc_b   = (const float*)d_in[2];
  p.self_w0 = (const float*)d_in[3];  p.self_b0 = (const float*)d_in[4];
  p.self_w1 = (const float*)d_in[5];  p.self_b1 = (const float*)d_in[6];
  p.rel_w0  = (const float*)d_in[7];  p.rel_b0  = (const float*)d_in[8];
  p.rel_w1  = (const float*)d_in[9];  p.rel_b1  = (const float*)d_in[10];
  p.rel_w2  = (const float*)d_in[11]; p.rel_b2  = (const float*)d_in[12];
  p.att_w0  = (const float*)d_in[13]; p.att_b0  = (const float*)d_in[14];
  p.att_w1  = (const float*)d_in[15]; p.att_b1  = (const float*)d_in[16];
  p.att_w2  = (const float*)d_in[17]; p.att_b2  = (const float*)d_in[18];
  p.aff_w0  = (const float*)d_in[19]; p.aff_b0  = (const float*)d_in[20];
  p.aff_w1  = (const float*)d_in[21]; p.aff_b1  = (const float*)d_in[22];
  p.aff_w2  = (const float*)d_in[23]; p.aff_b2  = (const float*)d_in[24];
  p.out_w0  = (const float*)d_in[25]; p.out_b0  = (const float*)d_in[26];
  p.out_w1  = (const float*)d_in[27]; p.out_b1  = (const float*)d_in[28];
  p.out     = (float*)d_out;

  int N = in_sizes[0] / (NOBJ * (CL / 2));
  dynamics_kernel<<<N, 256>>>(p);
}

// round 10
// speedup vs baseline: 2.5424x; 1.1290x over previous
#include <cuda_runtime.h>
#include <math.h>
#include <stdint.h>

#define CL 32
#define NOBJ 32

struct Params {
  const float *s;
  const float *enc_w, *enc_b;
  const float *self_w0, *self_b0, *self_w1, *self_b1;
  const float *rel_w0, *rel_b0, *rel_w1, *rel_b1, *rel_w2, *rel_b2;
  const float *att_w0, *att_b0, *att_w1, *att_b1, *att_w2, *att_b2;
  const float *aff_w0, *aff_b0, *aff_w1, *aff_b1, *aff_w2, *aff_b2;
  const float *out_w0, *out_b0, *out_w1, *out_b1;
  float *out;
};

// Transpose-reduce: lane j holds v[c] for c=0..31; lane m gets sum_j v[m].
// 31 shuffles. (R2-proven zero-lmem.)
__device__ __forceinline__ float reduce_t32(const float v[32], int lane) {
  float b16[16];
  #pragma unroll
  for (int t = 0; t < 16; ++t) {
    float lo = v[t], hi = v[t + 16];
    float send = (lane & 16) ? lo : hi;
    float keep = (lane & 16) ? hi : lo;
    b16[t] = keep + __shfl_xor_sync(0xffffffffu, send, 16);
  }
  float b8[8];
  #pragma unroll
  for (int t = 0; t < 8; ++t) {
    float lo = b16[t], hi = b16[t + 8];
    float send = (lane & 8) ? lo : hi;
    float keep = (lane & 8) ? hi : lo;
    b8[t] = keep + __shfl_xor_sync(0xffffffffu, send, 8);
  }
  float b4[4];
  #pragma unroll
  for (int t = 0; t < 4; ++t) {
    float lo = b8[t], hi = b8[t + 4];
    float send = (lane & 4) ? lo : hi;
    float keep = (lane & 4) ? hi : lo;
    b4[t] = keep + __shfl_xor_sync(0xffffffffu, send, 4);
  }
  float b2[2];
  #pragma unroll
  for (int t = 0; t < 2; ++t) {
    float lo = b4[t], hi = b4[t + 2];
    float send = (lane & 2) ? lo : hi;
    float keep = (lane & 2) ? hi : lo;
    b2[t] = keep + __shfl_xor_sync(0xffffffffu, send, 2);
  }
  float lo = b2[0], hi = b2[1];
  float send = (lane & 1) ? lo : hi;
  float keep = (lane & 1) ? hi : lo;
  return keep + __shfl_xor_sync(0xffffffffu, send, 1);
}

// Core pair accumulation for TWO i-rows sharing one weight stream (R2-identical).
#define PAIR_STEP(COMP, KOFF)                                                  \
  {                                                                            \
    float v1 = fmaxf(fmaf(dist1, wd.COMP, a1.COMP + ct.COMP), 0.0f);           \
    float v2 = fmaxf(fmaf(dist2, wd.COMP, a2.COMP + ct.COMP), 0.0f);           \
    const float4* wr = wb4 + (k4 * 4 + KOFF) * 8;                              \
    _Pragma("unroll")                                                          \
    for (int m4 = 0; m4 < 8; ++m4) {                                           \
      float4 q = wr[m4];                                                       \
      acc1[4*m4+0] = fmaf(v1, q.x, acc1[4*m4+0]);                              \
      acc2[4*m4+0] = fmaf(v2, q.x, acc2[4*m4+0]);                              \
      acc1[4*m4+1] = fmaf(v1, q.y, acc1[4*m4+1]);                              \
      acc2[4*m4+1] = fmaf(v2, q.y, acc2[4*m4+1]);                              \
      acc1[4*m4+2] = fmaf(v1, q.z, acc1[4*m4+2]);                              \
      acc2[4*m4+2] = fmaf(v2, q.z, acc2[4*m4+2]);                              \
      acc1[4*m4+3] = fmaf(v1, q.w, acc1[4*m4+3]);                              \
      acc2[4*m4+3] = fmaf(v2, q.w, acc2[4*m4+3]);                              \
    }                                                                          \
  }

__device__ __forceinline__ void pair_accum2(
    const float* __restrict__ proj_a, const float4* __restrict__ c4,
    const float4* __restrict__ wd4v, const float4* __restrict__ wb4,
    const float* __restrict__ bias1,
    float dist1, float dist2, int i1, int i2, int j,
    float acc1[32], float acc2[32])
{
  #pragma unroll
  for (int m = 0; m < 32; ++m) { float b = bias1[m]; acc1[m] = b; acc2[m] = b; }
  const float4* a1p = reinterpret_cast<const float4*>(proj_a + i1 * 64);
  const float4* a2p = reinterpret_cast<const float4*>(proj_a + i2 * 64);
  #pragma unroll
  for (int k4 = 0; k4 < 16; ++k4) {
    float4 ct = c4[k4 * 33 + j];
    float4 a1 = a1p[k4];
    float4 a2 = a2p[k4];
    float4 wd = wd4v[k4];
    PAIR_STEP(x, 0)
    PAIR_STEP(y, 1)
    PAIR_STEP(z, 2)
    PAIR_STEP(w, 3)
  }
}

__global__ void __launch_bounds__(256, 2) dynamics_kernel(Params p)
{
  // ---- shared (~42 KB) ----
  __shared__ __align__(16) float s2[NOBJ * CL];
  __shared__ __align__(16) float proj_a[NOBJ * 64];     // later t1/t2
  __shared__ __align__(16) float proj_c[16 * 33 * 4];
  __shared__ __align__(16) float wbuf[2048];            // W1; later t3
  __shared__ __align__(16) float sdyn[NOBJ * CL];
  __shared__ __align__(16) float ssm[NOBJ * CL];        // h1 scratch, then S
  __shared__ __align__(16) float attv[NOBJ * CL];       // ssrc scratch, then att
  __shared__ __align__(16) float4 wd4[16];
  __shared__ __align__(16) float miscA[32], miscB[32], miscC[32], avec[32];
  __shared__ float bA2s;

  const int n    = blockIdx.x;
  const int t    = threadIdx.x;
  const int lane = t & 31;
  const int w    = t >> 5;

  // ---- stage raw s (overlay in attv) ----
  {
    float* ssrc = attv;
    const float* sp = p.s + (size_t)n * (NOBJ * 16);
    for (int idx = t; idx < NOBJ * 16; idx += 256) ssrc[idx] = sp[idx];
  }
  __syncthreads();

  // ---- s2 = concat(s[:, :2], (s @ enc_w + enc_b)[:, 2:]) ----
  {
    const float* ssrc = attv;
    for (int idx = t; idx < NOBJ * CL; idx += 256) {
      int i = idx >> 5, c = idx & 31;
      float acc = __ldg(&p.enc_b[c]);
      #pragma unroll
      for (int k = 0; k < 16; ++k)
        acc = fmaf(ssrc[i * 16 + k], __ldg(&p.enc_w[k * 32 + c]), acc);
      s2[idx] = (c < 2) ? ssrc[i * 16 + c] : acc;
    }
  }
  __syncthreads();

  // ---- self branch: paired channels, float2 weight loads ----
  for (int idx = t; idx < 512; idx += 256) {
    int i = idx >> 4, c = (idx & 15) * 2;
    float2 b = __ldg(reinterpret_cast<const float2*>(&p.self_b0[c]));
    float acc0 = b.x, acc1 = b.y;
    #pragma unroll
    for (int k = 0; k < 32; ++k) {
      float x = s2[i * 32 + k];
      float2 wv = __ldg(reinterpret_cast<const float2*>(&p.self_w0[k * 32 + c]));
      acc0 = fmaf(x, wv.x, acc0);
      acc1 = fmaf(x, wv.y, acc1);
    }
    ssm[i * 32 + c]     = fmaxf(acc0, 0.0f);
    ssm[i * 32 + c + 1] = fmaxf(acc1, 0.0f);
  }
  __syncthreads();
  for (int idx = t; idx < 512; idx += 256) {
    int i = idx >> 4, c = (idx & 15) * 2;
    float2 b = __ldg(reinterpret_cast<const float2*>(&p.self_b1[c]));
    float acc0 = b.x + ssm[i * 32 + c];
    float acc1 = b.y + ssm[i * 32 + c + 1];
    #pragma unroll
    for (int k = 0; k < 32; ++k) {
      float x = ssm[i * 32 + k];
      float2 wv = __ldg(reinterpret_cast<const float2*>(&p.self_w1[k * 32 + c]));
      acc0 = fmaf(x, wv.x, acc0);
      acc1 = fmaf(x, wv.y, acc1);
    }
    sdyn[i * 32 + c]     = acc0;
    sdyn[i * 32 + c + 1] = acc1;
  }
  __syncthreads();

  const int j = lane;
  const float qx = s2[j * 32 + 0], qy = s2[j * 32 + 1];

  #pragma unroll 1
  for (int br = 0; br < 2; ++br) {
    const float* W0  = br ? p.rel_w0 : p.att_w0;
    const float* B0  = br ? p.rel_b0 : p.att_b0;
    const float* W1  = br ? p.rel_w1 : p.att_w1;
    const float* B1s = br ? p.rel_b1 : p.att_b1;

    // ---- stage W1 -> smem ----
    {
      const float4* src = reinterpret_cast<const float4*>(W1);
      float4* dst = reinterpret_cast<float4*>(wbuf);
      for (int idx = t; idx < 512; idx += 256) dst[idx] = __ldg(src + idx);
    }
    if (t < 64) reinterpret_cast<float*>(wd4)[t] = __ldg(&W0[64 * 64 + t]);
    else if (t < 96) {
      int c = t - 64;
      miscA[c] = __ldg(&B1s[c]);
      if (!br) miscB[c] = __ldg(&p.att_w2[c]);
      else     miscC[c] = __ldg(&p.rel_b2[c]);
    } else if (t == 96 && !br) {
      bA2s = __ldg(&p.att_b2[0]);
    }

    // ---- projections: thread = (io, k-pair), float2 weight loads ----
    for (int idx = t; idx < 1024; idx += 256) {
      int io = idx >> 5, k = (idx & 31) * 2;
      float a0 = 0.f, a1 = 0.f, c0 = 0.f, c1 = 0.f;
      #pragma unroll
      for (int cc = 0; cc < 32; ++cc) {
        float sv = s2[io * 32 + cc];
        float2 wa = __ldg(reinterpret_cast<const float2*>(&W0[cc * 64 + k]));
        float2 wc = __ldg(reinterpret_cast<const float2*>(&W0[(32 + cc) * 64 + k]));
        a0 = fmaf(sv, wa.x, a0);
        a1 = fmaf(sv, wa.y, a1);
        c0 = fmaf(sv, wc.x, c0);
        c1 = fmaf(sv, wc.y, c1);
      }
      float2 bv = __ldg(reinterpret_cast<const float2*>(&B0[k]));
      proj_a[io * 64 + k]     = a0 + bv.x;
      proj_a[io * 64 + k + 1] = a1 + bv.y;
      int g = (k >> 2) * 33 + io;          // k even: k and k+1 share the group
      proj_c[g * 4 + (k & 3)]     = c0;
      proj_c[g * 4 + (k & 3) + 1] = c1;
    }
    __syncthreads();

    #pragma unroll 1
    for (int it = 0; it < 2; ++it) {
      const int i1 = w * 4 + it * 2;
      const int i2 = i1 + 1;
      float dx1 = s2[i1 * 32 + 0] - qx, dy1 = s2[i1 * 32 + 1] - qy;
      float dx2 = s2[i2 * 32 + 0] - qx, dy2 = s2[i2 * 32 + 1] - qy;
      float dist1 = fmaf(dx1, dx1, dy1 * dy1);
      float dist2 = fmaf(dx2, dx2, dy2 * dy2);

      float acc1[32], acc2[32];
      pair_accum2(proj_a, reinterpret_cast<const float4*>(proj_c), wd4,
                  reinterpret_cast<const float4*>(wbuf), miscA,
                  dist1, dist2, i1, i2, j, acc1, acc2);

      if (!br) {
        float l1 = bA2s, l2 = bA2s;
        #pragma unroll
        for (int m = 0; m < 32; ++m) {
          float wm = miscB[m];
          l1 = fmaf(fmaxf(acc1[m], 0.0f), wm, l1);
          l2 = fmaf(fmaxf(acc2[m], 0.0f), wm, l2);
        }
        attv[i1 * 32 + j] = (j == i1) ? 0.0f : expf(l1);
        attv[i2 * 32 + j] = (j == i2) ? 0.0f : expf(l2);
      } else {
        float at1 = attv[i1 * 32 + j];
        float at2 = attv[i2 * 32 + j];
        #pragma unroll
        for (int m = 0; m < 32; ++m) acc1[m] = at1 * fmaxf(acc1[m], 0.0f);
        #pragma unroll
        for (int m = 0; m < 32; ++m) acc2[m] = at2 * fmaxf(acc2[m], 0.0f);

        float S1 = reduce_t32(acc1, lane);
        float S2 = reduce_t32(acc2, lane);
        float as1 = at1, as2 = at2;
        #pragma unroll
        for (int o = 16; o >= 1; o >>= 1) {
          as1 += __shfl_xor_sync(0xffffffffu, as1, o);
          as2 += __shfl_xor_sync(0xffffffffu, as2, o);
        }
        ssm[i1 * 32 + lane] = S1;
        ssm[i2 * 32 + lane] = S2;
        if (lane == 0) { avec[i1] = as1; avec[i2] = as2; }
      }
    }
    __syncthreads();
  }

  // ---- dyn = self_dyn + S@W2 + A*b2 + S (paired channels) ----
  for (int idx = t; idx < 512; idx += 256) {
    int i = idx >> 4, m = (idx & 15) * 2;
    float acc0 = sdyn[i * 32 + m]     + ssm[i * 32 + m]     + avec[i] * miscC[m];
    float acc1 = sdyn[i * 32 + m + 1] + ssm[i * 32 + m + 1] + avec[i] * miscC[m + 1];
    #pragma unroll
    for (int k = 0; k < 32; ++k) {
      float x = ssm[i * 32 + k];
      float2 wv = __ldg(reinterpret_cast<const float2*>(&p.rel_w2[k * 32 + m]));
      acc0 = fmaf(x, wv.x, acc0);
      acc1 = fmaf(x, wv.y, acc1);
    }
    sdyn[i * 32 + m]     = acc0;
    sdyn[i * 32 + m + 1] = acc1;
  }
  __syncthreads();

  // ---- tail MLP chain (paired channels, float2 weight loads) ----
  float* t1 = proj_a;
  float* t2 = proj_a + 1024;
  float* t3 = wbuf;

  for (int idx = t; idx < 512; idx += 256) {
    int i = idx >> 4, c = (idx & 15) * 2;
    float2 b = __ldg(reinterpret_cast<const float2*>(&p.aff_b0[c]));
    float acc0 = b.x, acc1 = b.y;
    #pragma unroll
    for (int k = 0; k < 32; ++k) {
      float x = sdyn[i * 32 + k];
      float2 wv = __ldg(reinterpret_cast<const float2*>(&p.aff_w0[k * 32 + c]));
      acc0 = fmaf(x, wv.x, acc0);
      acc1 = fmaf(x, wv.y, acc1);
    }
    t1[i * 32 + c]     = tanhf(acc0);
    t1[i * 32 + c + 1] = tanhf(acc1);
  }
  __syncthreads();

  for (int idx = t; idx < 512; idx += 256) {
    int i = idx >> 4, c = (idx & 15) * 2;
    float2 b = __ldg(reinterpret_cast<const float2*>(&p.aff_b1[c]));
    float acc0 = b.x, acc1 = b.y;
    #pragma unroll
    for (int k = 0; k < 32; ++k) {
      float x = t1[i * 32 + k];
      float2 wv = __ldg(reinterpret_cast<const float2*>(&p.aff_w1[k * 32 + c]));
      acc0 = fmaf(x, wv.x, acc0);
      acc1 = fmaf(x, wv.y, acc1);
    }
    t2[i * 32 + c]     = tanhf(acc0) + t1[i * 32 + c];
    t2[i * 32 + c + 1] = tanhf(acc1) + t1[i * 32 + c + 1];
  }
  __syncthreads();

  for (int idx = t; idx < 512; idx += 256) {
    int i = idx >> 4, c = (idx & 15) * 2;
    float2 b = __ldg(reinterpret_cast<const float2*>(&p.aff_b2[c]));
    float acc0 = b.x, acc1 = b.y;
    #pragma unroll
    for (int k = 0; k < 32; ++k) {
      float x = t2[i * 32 + k];
      float2 wv = __ldg(reinterpret_cast<const float2*>(&p.aff_w2[k * 32 + c]));
      acc0 = fmaf(x, wv.x, acc0);
      acc1 = fmaf(x, wv.y, acc1);
    }
    t3[i * 32 + c]     = acc0;
    t3[i * 32 + c + 1] = acc1;
  }
  __syncthreads();

  for (int idx = t; idx < 512; idx += 256) {
    int i = idx >> 4, c = (idx & 15) * 2;
    float2 b = __ldg(reinterpret_cast<const float2*>(&p.out_b0[c]));
    float acc0 = b.x, acc1 = b.y;
    #pragma unroll
    for (int k = 0; k < 32; ++k) {
      float x = t3[i * 32 + k];
      float2 wv = __ldg(reinterpret_cast<const float2*>(&p.out_w0[k * 32 + c]));
      acc0 = fmaf(x, wv.x, acc0);
      acc1 = fmaf(x, wv.y, acc1);
    }
    #pragma unroll
    for (int k = 0; k < 32; ++k) {
      float x = s2[i * 32 + k];
      float2 wv = __ldg(reinterpret_cast<const float2*>(&p.out_w0[(32 + k) * 32 + c]));
      acc0 = fmaf(x, wv.x, acc0);
      acc1 = fmaf(x, wv.y, acc1);
    }
    t1[i * 32 + c]     = tanhf(acc0);
    t1[i * 32 + c + 1] = tanhf(acc1);
  }
  __syncthreads();

  float* og = p.out + (size_t)n * (NOBJ * CL);
  for (int idx = t; idx < 512; idx += 256) {
    int i = idx >> 4, c = (idx & 15) * 2;
    float2 b = __ldg(reinterpret_cast<const float2*>(&p.out_b1[c]));
    float acc0 = b.x + t1[i * 32 + c];
    float acc1 = b.y + t1[i * 32 + c + 1];
    #pragma unroll
    for (int k = 0; k < 32; ++k) {
      float x = t1[i * 32 + k];
      float2 wv = __ldg(reinterpret_cast<const float2*>(&p.out_w1[k * 32 + c]));
      acc0 = fmaf(x, wv.x, acc0);
      acc1 = fmaf(x, wv.y, acc1);
    }
    og[i * 32 + c]     = acc0;
    og[i * 32 + c + 1] = acc1;
  }
}

extern "C" void kernel_launch(void* const* d_in, const int* in_sizes, int n_in,
                              void* d_out, int out_size)
{
  Params p;
  p.s       = (const float*)d_in[0];
  p.enc_w   = (const float*)d_in[1];  p.enc_b   = (const float*)d_in[2];
  p.self_w0 = (const float*)d_in[3];  p.self_b0 = (const float*)d_in[4];
  p.self_w1 = (const float*)d_in[5];  p.self_b1 = (const float*)d_in[6];
  p.rel_w0  = (const float*)d_in[7];  p.rel_b0  = (const float*)d_in[8];
  p.rel_w1  = (const float*)d_in[9];  p.rel_b1  = (const float*)d_in[10];
  p.rel_w2  = (const float*)d_in[11]; p.rel_b2  = (const float*)d_in[12];
  p.att_w0  = (const float*)d_in[13]; p.att_b0  = (const float*)d_in[14];
  p.att_w1  = (const float*)d_in[15]; p.att_b1  = (const float*)d_in[16];
  p.att_w2  = (const float*)d_in[17]; p.att_b2  = (const float*)d_in[18];
  p.aff_w0  = (const float*)d_in[19]; p.aff_b0  = (const float*)d_in[20];
  p.aff_w1  = (const float*)d_in[21]; p.aff_b1  = (const float*)d_in[22];
  p.aff_w2  = (const float*)d_in[23]; p.aff_b2  = (const float*)d_in[24];
  p.out_w0  = (const float*)d_in[25]; p.out_b0  = (const float*)d_in[26];
  p.out_w1  = (const float*)d_in[27]; p.out_b1  = (const float*)d_in[28];
  p.out     = (float*)d_out;

  int N = in_sizes[0] / (NOBJ * (CL / 2));
  dynamics_kernel<<<N, 256>>>(p);
}

// round 12
// speedup vs baseline: 2.9370x; 1.1552x over previous
#include <cuda_runtime.h>
#include <math.h>
#include <stdint.h>

#define CL 32
#define NOBJ 32

struct Params {
  const float *s;
  const float *enc_w, *enc_b;
  const float *self_w0, *self_b0, *self_w1, *self_b1;
  const float *rel_w0, *rel_b0, *rel_w1, *rel_b1, *rel_w2, *rel_b2;
  const float *att_w0, *att_b0, *att_w1, *att_b1, *att_w2, *att_b2;
  const float *aff_w0, *aff_b0, *aff_w1, *aff_b1, *aff_w2, *aff_b2;
  const float *out_w0, *out_b0, *out_w1, *out_b1;
  float *out;
};

__device__ __forceinline__ uint32_t tf32_rna(float x) {
  uint32_t r;
  asm("cvt.rna.tf32.f32 %0, %1;" : "=r"(r) : "f"(x));
  return r;
}

// m16n8k8 tf32 MMA: D = A@B + D. A row-major, B col-major. 32-bit operands only.
#define MMA_TF32(c0, c1, c2, c3, a0, a1, a2, a3, b0, b1)                       \
  asm("mma.sync.aligned.m16n8k8.row.col.f32.tf32.tf32.f32 "                    \
      "{%0,%1,%2,%3}, {%4,%5,%6,%7}, {%8,%9}, {%0,%1,%2,%3};"                  \
      : "+f"(c0), "+f"(c1), "+f"(c2), "+f"(c3)                                 \
      : "r"(a0), "r"(a1), "r"(a2), "r"(a3), "r"(b0), "r"(b1))

#define FOR_NT(F) F(0) F(1) F(2) F(3)

__global__ void __launch_bounds__(256) dynamics_kernel(Params p)
{
  // ---- shared (~45.8 KB) ----
  __shared__ __align__(16) float s2[NOBJ * CL];           // 4 KB
  __shared__ __align__(16) float pa[NOBJ * 64];           // 8 KB; tail t1/t2
  __shared__ __align__(16) float ctT[33 * 64];            // 8.25 KB (row 32 = wd)
  __shared__ __align__(16) uint32_t WhT[32 * 64];         // 8 KB; tail t3 alias
  __shared__ __align__(16) uint32_t WlT[32 * 64];         // 8 KB; sdyn alias
  __shared__ __align__(16) float ssm[NOBJ * CL];          // 4 KB: S matrix
  __shared__ __align__(16) float attv[NOBJ * CL];         // 4 KB: ssrc / att / h1
  __shared__ __align__(16) float miscA[32], miscB[32], miscC[32], avec[32];
  __shared__ float bA2s;

  float* sdyn = reinterpret_cast<float*>(WlT);            // 1024 floats
  float* wdf  = ctT + 32 * 64;                            // 64 floats

  const int n    = blockIdx.x;
  const int t    = threadIdx.x;
  const int lane = t & 31;
  const int w    = t >> 5;
  const int gid  = lane >> 2;   // groupID
  const int tig  = lane & 3;    // threadID in group
  const int swz  = gid << 2;    // k-swizzle for ct/W smem

  // ---- stage raw s (overlay in attv) ----
  {
    float* ssrc = attv;
    const float* sp = p.s + (size_t)n * (NOBJ * 16);
    for (int idx = t; idx < NOBJ * 16; idx += 256) ssrc[idx] = sp[idx];
  }
  __syncthreads();

  // ---- s2 = concat(s[:, :2], (s @ enc_w + enc_b)[:, 2:]) ----
  {
    const float* ssrc = attv;
    for (int idx = t; idx < NOBJ * CL; idx += 256) {
      int i = idx >> 5, c = idx & 31;
      float acc = __ldg(&p.enc_b[c]);
      #pragma unroll
      for (int k = 0; k < 16; ++k)
        acc = fmaf(ssrc[i * 16 + k], __ldg(&p.enc_w[k * 32 + c]), acc);
      s2[idx] = (c < 2) ? ssrc[i * 16 + c] : acc;
    }
  }
  __syncthreads();

  // ================= PAIR PHASE (tensor cores, tf32 x3) =================
  #pragma unroll 1
  for (int br = 0; br < 2; ++br) {
    const float* W0  = br ? p.rel_w0 : p.att_w0;
    const float* B0  = br ? p.rel_b0 : p.att_b0;
    const float* W1  = br ? p.rel_w1 : p.att_w1;
    const float* B1s = br ? p.rel_b1 : p.att_b1;

    // ---- stage W1 split hi/lo into swizzled smem ----
    for (int e = t; e < 2048; e += 256) {
      int k = e >> 5, nn = e & 31;
      float wv = __ldg(&W1[e]);                 // W1[k*32+nn], coalesced
      uint32_t hi = tf32_rna(wv);
      uint32_t lo = tf32_rna(wv - __uint_as_float(hi));
      int a = nn * 64 + (k ^ ((nn & 7) << 2));
      WhT[a] = hi;
      WlT[a] = lo;
    }
    if (t < 64) wdf[t] = __ldg(&W0[64 * 64 + t]);
    else if (t < 96) {
      int c = t - 64;
      miscA[c] = __ldg(&B1s[c]);
      if (!br) miscB[c] = __ldg(&p.att_w2[c]);
      else     miscC[c] = __ldg(&p.rel_b2[c]);
    } else if (t == 96 && !br) {
      bA2s = __ldg(&p.att_b2[0]);
    }

    // ---- projections: pa (bias folded) and ctT (swizzled) ----
    for (int idx = t; idx < 1024; idx += 256) {
      int io = idx >> 5, k = (idx & 31) * 2;
      float a0 = 0.f, a1 = 0.f, c0 = 0.f, c1 = 0.f;
      #pragma unroll
      for (int cc = 0; cc < 32; ++cc) {
        float sv = s2[io * 32 + cc];
        float2 wa = __ldg(reinterpret_cast<const float2*>(&W0[cc * 64 + k]));
        float2 wc = __ldg(reinterpret_cast<const float2*>(&W0[(32 + cc) * 64 + k]));
        a0 = fmaf(sv, wa.x, a0);
        a1 = fmaf(sv, wa.y, a1);
        c0 = fmaf(sv, wc.x, c0);
        c1 = fmaf(sv, wc.y, c1);
      }
      float2 bv = __ldg(reinterpret_cast<const float2*>(&B0[k]));
      pa[io * 64 + k]     = a0 + bv.x;
      pa[io * 64 + k + 1] = a1 + bv.y;
      int ks = k ^ ((io & 7) << 2);           // swizzle preserves even pair
      ctT[io * 64 + ks]     = c0;
      ctT[io * 64 + ks + 1] = c1;
    }
    __syncthreads();

    const int n64_0 = (0 * 8 + gid) * 64;
    const int n64_1 = (1 * 8 + gid) * 64;
    const int n64_2 = (2 * 8 + gid) * 64;
    const int n64_3 = (3 * 8 + gid) * 64;

    #pragma unroll 1
    for (int q = 0; q < 4; ++q) {
      const int i   = w * 4 + q;
      const int i64 = i * 64;
      const int jA = gid, jB = gid + 8, jC = gid + 16, jD = gid + 24;
      const int jA64 = jA * 64, jB64 = jB * 64, jC64 = jC * 64, jD64 = jD * 64;

      float pix = s2[i * 32 + 0], piy = s2[i * 32 + 1];
      float dxA = pix - s2[jA * 32 + 0], dyA = piy - s2[jA * 32 + 1];
      float dxB = pix - s2[jB * 32 + 0], dyB = piy - s2[jB * 32 + 1];
      float dxC = pix - s2[jC * 32 + 0], dyC = piy - s2[jC * 32 + 1];
      float dxD = pix - s2[jD * 32 + 0], dyD = piy - s2[jD * 32 + 1];
      float dA = fmaf(dxA, dxA, dyA * dyA);
      float dB = fmaf(dxB, dxB, dyB * dyB);
      float dC = fmaf(dxC, dxC, dyC * dyC);
      float dD = fmaf(dxD, dxD, dyD * dyD);

      float bb0a = miscA[0  + 2 * tig], bb0b = miscA[0  + 2 * tig + 1];
      float bb1a = miscA[8  + 2 * tig], bb1b = miscA[8  + 2 * tig + 1];
      float bb2a = miscA[16 + 2 * tig], bb2b = miscA[16 + 2 * tig + 1];
      float bb3a = miscA[24 + 2 * tig], bb3b = miscA[24 + 2 * tig + 1];

#define DECL_C(nt)                                                             \
      float c0n##nt##_0 = bb##nt##a, c0n##nt##_1 = bb##nt##b,                  \
            c0n##nt##_2 = bb##nt##a, c0n##nt##_3 = bb##nt##b,                  \
            c1n##nt##_0 = bb##nt##a, c1n##nt##_1 = bb##nt##b,                  \
            c1n##nt##_2 = bb##nt##a, c1n##nt##_3 = bb##nt##b;
      FOR_NT(DECL_C)
#undef DECL_C

      #pragma unroll 2
      for (int kt = 0; kt < 8; ++kt) {
        const int k0  = kt * 8 + tig;
        const int k1  = k0 + 4;
        const int kk0 = k0 ^ swz;
        const int kk1 = k1 ^ swz;

        float pa0 = pa[i64 + k0], pa1 = pa[i64 + k1];
        float wk0 = wdf[k0],      wk1 = wdf[k1];

        float vA0 = fmaxf(fmaf(dA, wk0, pa0 + ctT[jA64 + kk0]), 0.f);
        float vB0 = fmaxf(fmaf(dB, wk0, pa0 + ctT[jB64 + kk0]), 0.f);
        float vC0 = fmaxf(fmaf(dC, wk0, pa0 + ctT[jC64 + kk0]), 0.f);
        float vD0 = fmaxf(fmaf(dD, wk0, pa0 + ctT[jD64 + kk0]), 0.f);
        float vA1 = fmaxf(fmaf(dA, wk1, pa1 + ctT[jA64 + kk1]), 0.f);
        float vB1 = fmaxf(fmaf(dB, wk1, pa1 + ctT[jB64 + kk1]), 0.f);
        float vC1 = fmaxf(fmaf(dC, wk1, pa1 + ctT[jC64 + kk1]), 0.f);
        float vD1 = fmaxf(fmaf(dD, wk1, pa1 + ctT[jD64 + kk1]), 0.f);

        uint32_t hA0 = tf32_rna(vA0), hB0 = tf32_rna(vB0);
        uint32_t hC0 = tf32_rna(vC0), hD0 = tf32_rna(vD0);
        uint32_t hA1 = tf32_rna(vA1), hB1 = tf32_rna(vB1);
        uint32_t hC1 = tf32_rna(vC1), hD1 = tf32_rna(vD1);
        uint32_t lA0 = tf32_rna(vA0 - __uint_as_float(hA0));
        uint32_t lB0 = tf32_rna(vB0 - __uint_as_float(hB0));
        uint32_t lC0 = tf32_rna(vC0 - __uint_as_float(hC0));
        uint32_t lD0 = tf32_rna(vD0 - __uint_as_float(hD0));
        uint32_t lA1 = tf32_rna(vA1 - __uint_as_float(hA1));
        uint32_t lB1 = tf32_rna(vB1 - __uint_as_float(hB1));
        uint32_t lC1 = tf32_rna(vC1 - __uint_as_float(hC1));
        uint32_t lD1 = tf32_rna(vD1 - __uint_as_float(hD1));

#define MMA_NT(nt) {                                                           \
        uint32_t bh0 = WhT[n64_##nt + kk0], bh1 = WhT[n64_##nt + kk1];         \
        uint32_t bl0 = WlT[n64_##nt + kk0], bl1 = WlT[n64_##nt + kk1];         \
        MMA_TF32(c0n##nt##_0, c0n##nt##_1, c0n##nt##_2, c0n##nt##_3,           \
                 hA0, hB0, hA1, hB1, bh0, bh1);                                \
        MMA_TF32(c0n##nt##_0, c0n##nt##_1, c0n##nt##_2, c0n##nt##_3,           \
                 lA0, lB0, lA1, lB1, bh0, bh1);                                \
        MMA_TF32(c0n##nt##_0, c0n##nt##_1, c0n##nt##_2, c0n##nt##_3,           \
                 hA0, hB0, hA1, hB1, bl0, bl1);                                \
        MMA_TF32(c1n##nt##_0, c1n##nt##_1, c1n##nt##_2, c1n##nt##_3,           \
                 hC0, hD0, hC1, hD1, bh0, bh1);                                \
        MMA_TF32(c1n##nt##_0, c1n##nt##_1, c1n##nt##_2, c1n##nt##_3,           \
                 lC0, lD0, lC1, lD1, bh0, bh1);                                \
        MMA_TF32(c1n##nt##_0, c1n##nt##_1, c1n##nt##_2, c1n##nt##_3,           \
                 hC0, hD0, hC1, hD1, bl0, bl1); }
        FOR_NT(MMA_NT)
#undef MMA_NT
      }

      if (!br) {
        // ---- att epilogue: logit = b2 + sum_n relu(C)*w2[n] ----
        float lgA = 0.f, lgB = 0.f, lgC = 0.f, lgD = 0.f;
#define ATT_NT(nt) {                                                           \
        float w2a = miscB[nt * 8 + 2 * tig], w2b = miscB[nt * 8 + 2 * tig + 1];\
        lgA = fmaf(fmaxf(c0n##nt##_0, 0.f), w2a, lgA);                         \
        lgA = fmaf(fmaxf(c0n##nt##_1, 0.f), w2b, lgA);                         \
        lgB = fmaf(fmaxf(c0n##nt##_2, 0.f), w2a, lgB);                         \
        lgB = fmaf(fmaxf(c0n##nt##_3, 0.f), w2b, lgB);                         \
        lgC = fmaf(fmaxf(c1n##nt##_0, 0.f), w2a, lgC);                         \
        lgC = fmaf(fmaxf(c1n##nt##_1, 0.f), w2b, lgC);                         \
        lgD = fmaf(fmaxf(c1n##nt##_2, 0.f), w2a, lgD);                         \
        lgD = fmaf(fmaxf(c1n##nt##_3, 0.f), w2b, lgD); }
        FOR_NT(ATT_NT)
#undef ATT_NT
        lgA += __shfl_xor_sync(0xffffffffu, lgA, 1);
        lgA += __shfl_xor_sync(0xffffffffu, lgA, 2);
        lgB += __shfl_xor_sync(0xffffffffu, lgB, 1);
        lgB += __shfl_xor_sync(0xffffffffu, lgB, 2);
        lgC += __shfl_xor_sync(0xffffffffu, lgC, 1);
        lgC += __shfl_xor_sync(0xffffffffu, lgC, 2);
        lgD += __shfl_xor_sync(0xffffffffu, lgD, 1);
        lgD += __shfl_xor_sync(0xffffffffu, lgD, 2);
        float aA = (jA == i) ? 0.f : expf(bA2s + lgA);
        float aB = (jB == i) ? 0.f : expf(bA2s + lgB);
        float aC = (jC == i) ? 0.f : expf(bA2s + lgC);
        float aD = (jD == i) ? 0.f : expf(bA2s + lgD);
        if (tig == 0) {
          attv[i * 32 + jA] = aA;
          attv[i * 32 + jB] = aB;
          attv[i * 32 + jC] = aC;
          attv[i * 32 + jD] = aD;
        }
      } else {
        // ---- rel epilogue: S[i,col] = sum_j att*relu(C); A[i] = sum_j att ----
        float atA = attv[i * 32 + jA];
        float atB = attv[i * 32 + jB];
        float atC = attv[i * 32 + jC];
        float atD = attv[i * 32 + jD];
#define REL_NT(nt)                                                             \
        float ps##nt##a = fmaf(atA, fmaxf(c0n##nt##_0, 0.f),                   \
                          fmaf(atB, fmaxf(c0n##nt##_2, 0.f),                   \
                          fmaf(atC, fmaxf(c1n##nt##_0, 0.f),                   \
                               atD * fmaxf(c1n##nt##_2, 0.f))));               \
        float ps##nt##b = fmaf(atA, fmaxf(c0n##nt##_1, 0.f),                   \
                          fmaf(atB, fmaxf(c0n##nt##_3, 0.f),                   \
                          fmaf(atC, fmaxf(c1n##nt##_1, 0.f),                   \
                               atD * fmaxf(c1n##nt##_3, 0.f))));
        FOR_NT(REL_NT)
#undef REL_NT
#define RED_NT(nt) {                                                           \
        ps##nt##a += __shfl_xor_sync(0xffffffffu, ps##nt##a, 4);               \
        ps##nt##a += __shfl_xor_sync(0xffffffffu, ps##nt##a, 8);               \
        ps##nt##a += __shfl_xor_sync(0xffffffffu, ps##nt##a, 16);              \
        ps##nt##b += __shfl_xor_sync(0xffffffffu, ps##nt##b, 4);               \
        ps##nt##b += __shfl_xor_sync(0xffffffffu, ps##nt##b, 8);               \
        ps##nt##b += __shfl_xor_sync(0xffffffffu, ps##nt##b, 16); }
        FOR_NT(RED_NT)
#undef RED_NT
        if (gid == 0) {
#define ST_NT(nt) {                                                            \
          ssm[i * 32 + nt * 8 + 2 * tig]     = ps##nt##a;                      \
          ssm[i * 32 + nt * 8 + 2 * tig + 1] = ps##nt##b; }
          FOR_NT(ST_NT)
#undef ST_NT
        }
        float asum = atA + atB + atC + atD;
        asum += __shfl_xor_sync(0xffffffffu, asum, 4);
        asum += __shfl_xor_sync(0xffffffffu, asum, 8);
        asum += __shfl_xor_sync(0xffffffffu, asum, 16);
        if (lane == 0) avec[i] = asum;
      }
    }
    __syncthreads();
  }

  // ---- self branch (after pair; h1 in attv, out to sdyn alias) ----
  for (int idx = t; idx < 512; idx += 256) {
    int i = idx >> 4, c = (idx & 15) * 2;
    float2 b = __ldg(reinterpret_cast<const float2*>(&p.self_b0[c]));
    float acc0 = b.x, acc1 = b.y;
    #pragma unroll
    for (int k = 0; k < 32; ++k) {
      float x = s2[i * 32 + k];
      float2 wv = __ldg(reinterpret_cast<const float2*>(&p.self_w0[k * 32 + c]));
      acc0 = fmaf(x, wv.x, acc0);
      acc1 = fmaf(x, wv.y, acc1);
    }
    attv[i * 32 + c]     = fmaxf(acc0, 0.0f);
    attv[i * 32 + c + 1] = fmaxf(acc1, 0.0f);
  }
  __syncthreads();
  for (int idx = t; idx < 512; idx += 256) {
    int i = idx >> 4, c = (idx & 15) * 2;
    float2 b = __ldg(reinterpret_cast<const float2*>(&p.self_b1[c]));
    float acc0 = b.x + attv[i * 32 + c];
    float acc1 = b.y + attv[i * 32 + c + 1];
    #pragma unroll
    for (int k = 0; k < 32; ++k) {
      float x = attv[i * 32 + k];
      float2 wv = __ldg(reinterpret_cast<const float2*>(&p.self_w1[k * 32 + c]));
      acc0 = fmaf(x, wv.x, acc0);
      acc1 = fmaf(x, wv.y, acc1);
    }
    sdyn[i * 32 + c]     = acc0;
    sdyn[i * 32 + c + 1] = acc1;
  }
  __syncthreads();

  // ---- dyn = self_dyn + S@W2 + A*b2 + S ----
  for (int idx = t; idx < 512; idx += 256) {
    int i = idx >> 4, m = (idx & 15) * 2;
    float acc0 = sdyn[i * 32 + m]     + ssm[i * 32 + m]     + avec[i] * miscC[m];
    float acc1 = sdyn[i * 32 + m + 1] + ssm[i * 32 + m + 1] + avec[i] * miscC[m + 1];
    #pragma unroll
    for (int k = 0; k < 32; ++k) {
      float x = ssm[i * 32 + k];
      float2 wv = __ldg(reinterpret_cast<const float2*>(&p.rel_w2[k * 32 + m]));
      acc0 = fmaf(x, wv.x, acc0);
      acc1 = fmaf(x, wv.y, acc1);
    }
    sdyn[i * 32 + m]     = acc0;
    sdyn[i * 32 + m + 1] = acc1;
  }
  __syncthreads();

  // ---- tail MLP chain ----
  float* t1 = pa;
  float* t2 = pa + 1024;
  float* t3 = reinterpret_cast<float*>(WhT);

  for (int idx = t; idx < 512; idx += 256) {
    int i = idx >> 4, c = (idx & 15) * 2;
    float2 b = __ldg(reinterpret_cast<const float2*>(&p.aff_b0[c]));
    float acc0 = b.x, acc1 = b.y;
    #pragma unroll
    for (int k = 0; k < 32; ++k) {
      float x = sdyn[i * 32 + k];
      float2 wv = __ldg(reinterpret_cast<const float2*>(&p.aff_w0[k * 32 + c]));
      acc0 = fmaf(x, wv.x, acc0);
      acc1 = fmaf(x, wv.y, acc1);
    }
    t1[i * 32 + c]     = tanhf(acc0);
    t1[i * 32 + c + 1] = tanhf(acc1);
  }
  __syncthreads();

  for (int idx = t; idx < 512; idx += 256) {
    int i = idx >> 4, c = (idx & 15) * 2;
    float2 b = __ldg(reinterpret_cast<const float2*>(&p.aff_b1[c]));
    float acc0 = b.x, acc1 = b.y;
    #pragma unroll
    for (int k = 0; k < 32; ++k) {
      float x = t1[i * 32 + k];
      float2 wv = __ldg(reinterpret_cast<const float2*>(&p.aff_w1[k * 32 + c]));
      acc0 = fmaf(x, wv.x, acc0);
      acc1 = fmaf(x, wv.y, acc1);
    }
    t2[i * 32 + c]     = tanhf(acc0) + t1[i * 32 + c];
    t2[i * 32 + c + 1] = tanhf(acc1) + t1[i * 32 + c + 1];
  }
  __syncthreads();

  for (int idx = t; idx < 512; idx += 256) {
    int i = idx >> 4, c = (idx & 15) * 2;
    float2 b = __ldg(reinterpret_cast<const float2*>(&p.aff_b2[c]));
    float acc0 = b.x, acc1 = b.y;
    #pragma unroll
    for (int k = 0; k < 32; ++k) {
      float x = t2[i * 32 + k];
      float2 wv = __ldg(reinterpret_cast<const float2*>(&p.aff_w2[k * 32 + c]));
      acc0 = fmaf(x, wv.x, acc0);
      acc1 = fmaf(x, wv.y, acc1);
    }
    t3[i * 32 + c]     = acc0;
    t3[i * 32 + c + 1] = acc1;
  }
  __syncthreads();

  for (int idx = t; idx < 512; idx += 256) {
    int i = idx >> 4, c = (idx & 15) * 2;
    float2 b = __ldg(reinterpret_cast<const float2*>(&p.out_b0[c]));
    float acc0 = b.x, acc1 = b.y;
    #pragma unroll
    for (int k = 0; k < 32; ++k) {
      float x = t3[i * 32 + k];
      float2 wv = __ldg(reinterpret_cast<const float2*>(&p.out_w0[k * 32 + c]));
      acc0 = fmaf(x, wv.x, acc0);
      acc1 = fmaf(x, wv.y, acc1);
    }
    #pragma unroll
    for (int k = 0; k < 32; ++k) {
      float x = s2[i * 32 + k];
      float2 wv = __ldg(reinterpret_cast<const float2*>(&p.out_w0[(32 + k) * 32 + c]));
      acc0 = fmaf(x, wv.x, acc0);
      acc1 = fmaf(x, wv.y, acc1);
    }
    t1[i * 32 + c]     = tanhf(acc0);
    t1[i * 32 + c + 1] = tanhf(acc1);
  }
  __syncthreads();

  float* og = p.out + (size_t)n * (NOBJ * CL);
  for (int idx = t; idx < 512; idx += 256) {
    int i = idx >> 4, c = (idx & 15) * 2;
    float2 b = __ldg(reinterpret_cast<const float2*>(&p.out_b1[c]));
    float acc0 = b.x + t1[i * 32 + c];
    float acc1 = b.y + t1[i * 32 + c + 1];
    #pragma unroll
    for (int k = 0; k < 32; ++k) {
      float x = t1[i * 32 + k];
      float2 wv = __ldg(reinterpret_cast<const float2*>(&p.out_w1[k * 32 + c]));
      acc0 = fmaf(x, wv.x, acc0);
      acc1 = fmaf(x, wv.y, acc1);
    }
    og[i * 32 + c]     = acc0;
    og[i * 32 + c + 1] = acc1;
  }
}

extern "C" void kernel_launch(void* const* d_in, const int* in_sizes, int n_in,
                              void* d_out, int out_size)
{
  Params p;
  p.s       = (const float*)d_in[0];
  p.enc_w   = (const float*)d_in[1];  p.enc_b   = (const float*)d_in[2];
  p.self_w0 = (const float*)d_in[3];  p.self_b0 = (const float*)d_in[4];
  p.self_w1 = (const float*)d_in[5];  p.self_b1 = (const float*)d_in[6];
  p.rel_w0  = (const float*)d_in[7];  p.rel_b0  = (const float*)d_in[8];
  p.rel_w1  = (const float*)d_in[9];  p.rel_b1  = (const float*)d_in[10];
  p.rel_w2  = (const float*)d_in[11]; p.rel_b2  = (const float*)d_in[12];
  p.att_w0  = (const float*)d_in[13]; p.att_b0  = (const float*)d_in[14];
  p.att_w1  = (const float*)d_in[15]; p.att_b1  = (const float*)d_in[16];
  p.att_w2  = (const float*)d_in[17]; p.att_b2  = (const float*)d_in[18];
  p.aff_w0  = (const float*)d_in[19]; p.aff_b0  = (const float*)d_in[20];
  p.aff_w1  = (const float*)d_in[21]; p.aff_b1  = (const float*)d_in[22];
  p.aff_w2  = (const float*)d_in[23]; p.aff_b2  = (const float*)d_in[24];
  p.out_w0  = (const float*)d_in[25]; p.out_b0  = (const float*)d_in[26];
  p.out_w1  = (const float*)d_in[27]; p.out_b1  = (const float*)d_in[28];
  p.out     = (float*)d_out;

  int N = in_sizes[0] / (NOBJ * (CL / 2));
  dynamics_kernel<<<N, 256>>>(p);
}

// round 13
// speedup vs baseline: 2.9906x; 1.0182x over previous
#include <cuda_runtime.h>
#include <math.h>
#include <stdint.h>

#define CL 32
#define NOBJ 32
#define PADW 68   // padded row stride (floats) — conflict-free without XOR

struct Params {
  const float *s;
  const float *enc_w, *enc_b;
  const float *self_w0, *self_b0, *self_w1, *self_b1;
  const float *rel_w0, *rel_b0, *rel_w1, *rel_b1, *rel_w2, *rel_b2;
  const float *att_w0, *att_b0, *att_w1, *att_b1, *att_w2, *att_b2;
  const float *aff_w0, *aff_b0, *aff_w1, *aff_b1, *aff_w2, *aff_b2;
  const float *out_w0, *out_b0, *out_w1, *out_b1;
  float *out;
};

__device__ __forceinline__ uint32_t tf32_rna(float x) {
  uint32_t r;
  asm("cvt.rna.tf32.f32 %0, %1;" : "=r"(r) : "f"(x));
  return r;
}

// m16n8k8 tf32 MMA: D = A@B + D. A row-major, B col-major. 32-bit operands only.
#define MMA_TF32(c0, c1, c2, c3, a0, a1, a2, a3, b0, b1)                       \
  asm("mma.sync.aligned.m16n8k8.row.col.f32.tf32.tf32.f32 "                    \
      "{%0,%1,%2,%3}, {%4,%5,%6,%7}, {%8,%9}, {%0,%1,%2,%3};"                  \
      : "+f"(c0), "+f"(c1), "+f"(c2), "+f"(c3)                                 \
      : "r"(a0), "r"(a1), "r"(a2), "r"(a3), "r"(b0), "r"(b1))

#define FOR_NT(F) F(0) F(1) F(2) F(3)

__global__ void __launch_bounds__(256) dynamics_kernel(Params p)
{
  // ---- shared (~47.4 KB) ----
  __shared__ __align__(16) float s2[NOBJ * CL];           // 4 KB
  __shared__ __align__(16) float pa[NOBJ * 64];           // 8 KB; tail t1/t2
  __shared__ __align__(16) float ctT[33 * PADW];          // 8.98 KB (row 32 = wd)
  __shared__ __align__(16) uint32_t WhT[32 * PADW];       // 8.7 KB; tail t3 alias
  __shared__ __align__(16) uint32_t WlT[32 * PADW];       // 8.7 KB; sdyn alias
  __shared__ __align__(16) float ssm[NOBJ * CL];          // 4 KB: S matrix
  __shared__ __align__(16) float attv[NOBJ * CL];         // 4 KB: ssrc / att / h1
  __shared__ __align__(16) float miscA[32], miscB[32], miscC[32], avec[32];
  __shared__ float bA2s;

  float* sdyn = reinterpret_cast<float*>(WlT);            // 1024 floats
  float* wdf  = ctT + 32 * PADW;                          // 64 floats

  const int n    = blockIdx.x;
  const int t    = threadIdx.x;
  const int lane = t & 31;
  const int w    = t >> 5;
  const int gid  = lane >> 2;   // groupID
  const int tig  = lane & 3;    // threadID in group

  // ---- stage raw s (overlay in attv) ----
  {
    float* ssrc = attv;
    const float* sp = p.s + (size_t)n * (NOBJ * 16);
    for (int idx = t; idx < NOBJ * 16; idx += 256) ssrc[idx] = sp[idx];
  }
  __syncthreads();

  // ---- s2 = concat(s[:, :2], (s @ enc_w + enc_b)[:, 2:]) ----
  {
    const float* ssrc = attv;
    for (int idx = t; idx < NOBJ * CL; idx += 256) {
      int i = idx >> 5, c = idx & 31;
      float acc = __ldg(&p.enc_b[c]);
      #pragma unroll
      for (int k = 0; k < 16; ++k)
        acc = fmaf(ssrc[i * 16 + k], __ldg(&p.enc_w[k * 32 + c]), acc);
      s2[idx] = (c < 2) ? ssrc[i * 16 + c] : acc;
    }
  }
  __syncthreads();

  // ================= PAIR PHASE (tensor cores, tf32 x3) =================
  #pragma unroll 1
  for (int br = 0; br < 2; ++br) {
    const float* W0  = br ? p.rel_w0 : p.att_w0;
    const float* B0  = br ? p.rel_b0 : p.att_b0;
    const float* W1  = br ? p.rel_w1 : p.att_w1;
    const float* B1s = br ? p.rel_b1 : p.att_b1;

    // ---- stage W1 split hi/lo into padded smem (no swizzle) ----
    for (int e = t; e < 2048; e += 256) {
      int k = e >> 5, nn = e & 31;
      float wv = __ldg(&W1[e]);                 // W1[k*32+nn], coalesced
      uint32_t hi = tf32_rna(wv);
      uint32_t lo = tf32_rna(wv - __uint_as_float(hi));
      int a = nn * PADW + k;
      WhT[a] = hi;
      WlT[a] = lo;
    }
    if (t < 64) wdf[t] = __ldg(&W0[64 * 64 + t]);
    else if (t < 96) {
      int c = t - 64;
      miscA[c] = __ldg(&B1s[c]);
      if (!br) miscB[c] = __ldg(&p.att_w2[c]);
      else     miscC[c] = __ldg(&p.rel_b2[c]);
    } else if (t == 96 && !br) {
      bA2s = __ldg(&p.att_b2[0]);
    }

    // ---- projections: pa (bias folded) and ctT (padded) ----
    for (int idx = t; idx < 1024; idx += 256) {
      int io = idx >> 5, k = (idx & 31) * 2;
      float a0 = 0.f, a1 = 0.f, c0 = 0.f, c1 = 0.f;
      #pragma unroll
      for (int cc = 0; cc < 32; ++cc) {
        float sv = s2[io * 32 + cc];
        float2 wa = __ldg(reinterpret_cast<const float2*>(&W0[cc * 64 + k]));
        float2 wc = __ldg(reinterpret_cast<const float2*>(&W0[(32 + cc) * 64 + k]));
        a0 = fmaf(sv, wa.x, a0);
        a1 = fmaf(sv, wa.y, a1);
        c0 = fmaf(sv, wc.x, c0);
        c1 = fmaf(sv, wc.y, c1);
      }
      float2 bv = __ldg(reinterpret_cast<const float2*>(&B0[k]));
      pa[io * 64 + k]     = a0 + bv.x;
      pa[io * 64 + k + 1] = a1 + bv.y;
      ctT[io * PADW + k]     = c0;
      ctT[io * PADW + k + 1] = c1;
    }
    __syncthreads();

    const int n68_0 = (0 * 8 + gid) * PADW;
    const int n68_1 = (1 * 8 + gid) * PADW;
    const int n68_2 = (2 * 8 + gid) * PADW;
    const int n68_3 = (3 * 8 + gid) * PADW;

    #pragma unroll 1
    for (int q = 0; q < 4; ++q) {
      const int i   = w * 4 + q;
      const int i64 = i * 64;
      const int jA = gid, jB = gid + 8, jC = gid + 16, jD = gid + 24;
      const int jA68 = jA * PADW, jB68 = jB * PADW;
      const int jC68 = jC * PADW, jD68 = jD * PADW;

      float pix = s2[i * 32 + 0], piy = s2[i * 32 + 1];
      float dxA = pix - s2[jA * 32 + 0], dyA = piy - s2[jA * 32 + 1];
      float dxB = pix - s2[jB * 32 + 0], dyB = piy - s2[jB * 32 + 1];
      float dxC = pix - s2[jC * 32 + 0], dyC = piy - s2[jC * 32 + 1];
      float dxD = pix - s2[jD * 32 + 0], dyD = piy - s2[jD * 32 + 1];
      float dA = fmaf(dxA, dxA, dyA * dyA);
      float dB = fmaf(dxB, dxB, dyB * dyB);
      float dC = fmaf(dxC, dxC, dyC * dyC);
      float dD = fmaf(dxD, dxD, dyD * dyD);

      float bb0a = miscA[0  + 2 * tig], bb0b = miscA[0  + 2 * tig + 1];
      float bb1a = miscA[8  + 2 * tig], bb1b = miscA[8  + 2 * tig + 1];
      float bb2a = miscA[16 + 2 * tig], bb2b = miscA[16 + 2 * tig + 1];
      float bb3a = miscA[24 + 2 * tig], bb3b = miscA[24 + 2 * tig + 1];

#define DECL_C(nt)                                                             \
      float c0n##nt##_0 = bb##nt##a, c0n##nt##_1 = bb##nt##b,                  \
            c0n##nt##_2 = bb##nt##a, c0n##nt##_3 = bb##nt##b,                  \
            c1n##nt##_0 = bb##nt##a, c1n##nt##_1 = bb##nt##b,                  \
            c1n##nt##_2 = bb##nt##a, c1n##nt##_3 = bb##nt##b;
      FOR_NT(DECL_C)
#undef DECL_C

      #pragma unroll 2
      for (int kt = 0; kt < 8; ++kt) {
        const int k0 = kt * 8 + tig;
        const int k1 = k0 + 4;

        float pa0 = pa[i64 + k0], pa1 = pa[i64 + k1];
        float wk0 = wdf[k0],      wk1 = wdf[k1];

        float vA0 = fmaxf(fmaf(dA, wk0, pa0 + ctT[jA68 + k0]), 0.f);
        float vB0 = fmaxf(fmaf(dB, wk0, pa0 + ctT[jB68 + k0]), 0.f);
        float vC0 = fmaxf(fmaf(dC, wk0, pa0 + ctT[jC68 + k0]), 0.f);
        float vD0 = fmaxf(fmaf(dD, wk0, pa0 + ctT[jD68 + k0]), 0.f);
        float vA1 = fmaxf(fmaf(dA, wk1, pa1 + ctT[jA68 + k1]), 0.f);
        float vB1 = fmaxf(fmaf(dB, wk1, pa1 + ctT[jB68 + k1]), 0.f);
        float vC1 = fmaxf(fmaf(dC, wk1, pa1 + ctT[jC68 + k1]), 0.f);
        float vD1 = fmaxf(fmaf(dD, wk1, pa1 + ctT[jD68 + k1]), 0.f);

        uint32_t hA0 = tf32_rna(vA0), hB0 = tf32_rna(vB0);
        uint32_t hC0 = tf32_rna(vC0), hD0 = tf32_rna(vD0);
        uint32_t hA1 = tf32_rna(vA1), hB1 = tf32_rna(vB1);
        uint32_t hC1 = tf32_rna(vC1), hD1 = tf32_rna(vD1);
        uint32_t lA0 = tf32_rna(vA0 - __uint_as_float(hA0));
        uint32_t lB0 = tf32_rna(vB0 - __uint_as_float(hB0));
        uint32_t lC0 = tf32_rna(vC0 - __uint_as_float(hC0));
        uint32_t lD0 = tf32_rna(vD0 - __uint_as_float(hD0));
        uint32_t lA1 = tf32_rna(vA1 - __uint_as_float(hA1));
        uint32_t lB1 = tf32_rna(vB1 - __uint_as_float(hB1));
        uint32_t lC1 = tf32_rna(vC1 - __uint_as_float(hC1));
        uint32_t lD1 = tf32_rna(vD1 - __uint_as_float(hD1));

#define MMA_NT(nt) {                                                           \
        uint32_t bh0 = WhT[n68_##nt + k0], bh1 = WhT[n68_##nt + k1];           \
        uint32_t bl0 = WlT[n68_##nt + k0], bl1 = WlT[n68_##nt + k1];           \
        MMA_TF32(c0n##nt##_0, c0n##nt##_1, c0n##nt##_2, c0n##nt##_3,           \
                 hA0, hB0, hA1, hB1, bh0, bh1);                                \
        MMA_TF32(c0n##nt##_0, c0n##nt##_1, c0n##nt##_2, c0n##nt##_3,           \
                 lA0, lB0, lA1, lB1, bh0, bh1);                                \
        MMA_TF32(c0n##nt##_0, c0n##nt##_1, c0n##nt##_2, c0n##nt##_3,           \
                 hA0, hB0, hA1, hB1, bl0, bl1);                                \
        MMA_TF32(c1n##nt##_0, c1n##nt##_1, c1n##nt##_2, c1n##nt##_3,           \
                 hC0, hD0, hC1, hD1, bh0, bh1);                                \
        MMA_TF32(c1n##nt##_0, c1n##nt##_1, c1n##nt##_2, c1n##nt##_3,           \
                 lC0, lD0, lC1, lD1, bh0, bh1);                                \
        MMA_TF32(c1n##nt##_0, c1n##nt##_1, c1n##nt##_2, c1n##nt##_3,           \
                 hC0, hD0, hC1, hD1, bl0, bl1); }
        FOR_NT(MMA_NT)
#undef MMA_NT
      }

      if (!br) {
        // ---- att epilogue: logit = b2 + sum_n relu(C)*w2[n] ----
        float lgA = 0.f, lgB = 0.f, lgC = 0.f, lgD = 0.f;
#define ATT_NT(nt) {                                                           \
        float w2a = miscB[nt * 8 + 2 * tig], w2b = miscB[nt * 8 + 2 * tig + 1];\
        lgA = fmaf(fmaxf(c0n##nt##_0, 0.f), w2a, lgA);                         \
        lgA = fmaf(fmaxf(c0n##nt##_1, 0.f), w2b, lgA);                         \
        lgB = fmaf(fmaxf(c0n##nt##_2, 0.f), w2a, lgB);                         \
        lgB = fmaf(fmaxf(c0n##nt##_3, 0.f), w2b, lgB);                         \
        lgC = fmaf(fmaxf(c1n##nt##_0, 0.f), w2a, lgC);                         \
        lgC = fmaf(fmaxf(c1n##nt##_1, 0.f), w2b, lgC);                         \
        lgD = fmaf(fmaxf(c1n##nt##_2, 0.f), w2a, lgD);                         \
        lgD = fmaf(fmaxf(c1n##nt##_3, 0.f), w2b, lgD); }
        FOR_NT(ATT_NT)
#undef ATT_NT
        lgA += __shfl_xor_sync(0xffffffffu, lgA, 1);
        lgA += __shfl_xor_sync(0xffffffffu, lgA, 2);
        lgB += __shfl_xor_sync(0xffffffffu, lgB, 1);
        lgB += __shfl_xor_sync(0xffffffffu, lgB, 2);
        lgC += __shfl_xor_sync(0xffffffffu, lgC, 1);
        lgC += __shfl_xor_sync(0xffffffffu, lgC, 2);
        lgD += __shfl_xor_sync(0xffffffffu, lgD, 1);
        lgD += __shfl_xor_sync(0xffffffffu, lgD, 2);
        float aA = (jA == i) ? 0.f : expf(bA2s + lgA);
        float aB = (jB == i) ? 0.f : expf(bA2s + lgB);
        float aC = (jC == i) ? 0.f : expf(bA2s + lgC);
        float aD = (jD == i) ? 0.f : expf(bA2s + lgD);
        if (tig == 0) {
          attv[i * 32 + jA] = aA;
          attv[i * 32 + jB] = aB;
          attv[i * 32 + jC] = aC;
          attv[i * 32 + jD] = aD;
        }
      } else {
        // ---- rel epilogue: S[i,col] = sum_j att*relu(C); A[i] = sum_j att ----
        float atA = attv[i * 32 + jA];
        float atB = attv[i * 32 + jB];
        float atC = attv[i * 32 + jC];
        float atD = attv[i * 32 + jD];
#define REL_NT(nt)                                                             \
        float ps##nt##a = fmaf(atA, fmaxf(c0n##nt##_0, 0.f),                   \
                          fmaf(atB, fmaxf(c0n##nt##_2, 0.f),                   \
                          fmaf(atC, fmaxf(c1n##nt##_0, 0.f),                   \
                               atD * fmaxf(c1n##nt##_2, 0.f))));               \
        float ps##nt##b = fmaf(atA, fmaxf(c0n##nt##_1, 0.f),                   \
                          fmaf(atB, fmaxf(c0n##nt##_3, 0.f),                   \
                          fmaf(atC, fmaxf(c1n##nt##_1, 0.f),                   \
                               atD * fmaxf(c1n##nt##_3, 0.f))));
        FOR_NT(REL_NT)
#undef REL_NT
#define RED_NT(nt) {                                                           \
        ps##nt##a += __shfl_xor_sync(0xffffffffu, ps##nt##a, 4);               \
        ps##nt##a += __shfl_xor_sync(0xffffffffu, ps##nt##a, 8);               \
        ps##nt##a += __shfl_xor_sync(0xffffffffu, ps##nt##a, 16);              \
        ps##nt##b += __shfl_xor_sync(0xffffffffu, ps##nt##b, 4);               \
        ps##nt##b += __shfl_xor_sync(0xffffffffu, ps##nt##b, 8);               \
        ps##nt##b += __shfl_xor_sync(0xffffffffu, ps##nt##b, 16); }
        FOR_NT(RED_NT)
#undef RED_NT
        if (gid == 0) {
#define ST_NT(nt) {                                                            \
          ssm[i * 32 + nt * 8 + 2 * tig]     = ps##nt##a;                      \
          ssm[i * 32 + nt * 8 + 2 * tig + 1] = ps##nt##b; }
          FOR_NT(ST_NT)
#undef ST_NT
        }
        float asum = atA + atB + atC + atD;
        asum += __shfl_xor_sync(0xffffffffu, asum, 4);
        asum += __shfl_xor_sync(0xffffffffu, asum, 8);
        asum += __shfl_xor_sync(0xffffffffu, asum, 16);
        if (lane == 0) avec[i] = asum;
      }
    }
    __syncthreads();
  }

  // ---- self branch (after pair; h1 in attv, out to sdyn alias) ----
  for (int idx = t; idx < 512; idx += 256) {
    int i = idx >> 4, c = (idx & 15) * 2;
    float2 b = __ldg(reinterpret_cast<const float2*>(&p.self_b0[c]));
    float acc0 = b.x, acc1 = b.y;
    #pragma unroll
    for (int k = 0; k < 32; ++k) {
      float x = s2[i * 32 + k];
      float2 wv = __ldg(reinterpret_cast<const float2*>(&p.self_w0[k * 32 + c]));
      acc0 = fmaf(x, wv.x, acc0);
      acc1 = fmaf(x, wv.y, acc1);
    }
    attv[i * 32 + c]     = fmaxf(acc0, 0.0f);
    attv[i * 32 + c + 1] = fmaxf(acc1, 0.0f);
  }
  __syncthreads();
  for (int idx = t; idx < 512; idx += 256) {
    int i = idx >> 4, c = (idx & 15) * 2;
    float2 b = __ldg(reinterpret_cast<const float2*>(&p.self_b1[c]));
    float acc0 = b.x + attv[i * 32 + c];
    float acc1 = b.y + attv[i * 32 + c + 1];
    #pragma unroll
    for (int k = 0; k < 32; ++k) {
      float x = attv[i * 32 + k];
      float2 wv = __ldg(reinterpret_cast<const float2*>(&p.self_w1[k * 32 + c]));
      acc0 = fmaf(x, wv.x, acc0);
      acc1 = fmaf(x, wv.y, acc1);
    }
    sdyn[i * 32 + c]     = acc0;
    sdyn[i * 32 + c + 1] = acc1;
  }
  __syncthreads();

  // ---- dyn = self_dyn + S@W2 + A*b2 + S ----
  for (int idx = t; idx < 512; idx += 256) {
    int i = idx >> 4, m = (idx & 15) * 2;
    float acc0 = sdyn[i * 32 + m]     + ssm[i * 32 + m]     + avec[i] * miscC[m];
    float acc1 = sdyn[i * 32 + m + 1] + ssm[i * 32 + m + 1] + avec[i] * miscC[m + 1];
    #pragma unroll
    for (int k = 0; k < 32; ++k) {
      float x = ssm[i * 32 + k];
      float2 wv = __ldg(reinterpret_cast<const float2*>(&p.rel_w2[k * 32 + m]));
      acc0 = fmaf(x, wv.x, acc0);
      acc1 = fmaf(x, wv.y, acc1);
    }
    sdyn[i * 32 + m]     = acc0;
    sdyn[i * 32 + m + 1] = acc1;
  }
  __syncthreads();

  // ---- tail MLP chain ----
  float* t1 = pa;
  float* t2 = pa + 1024;
  float* t3 = reinterpret_cast<float*>(WhT);

  for (int idx = t; idx < 512; idx += 256) {
    int i = idx >> 4, c = (idx & 15) * 2;
    float2 b = __ldg(reinterpret_cast<const float2*>(&p.aff_b0[c]));
    float acc0 = b.x, acc1 = b.y;
    #pragma unroll
    for (int k = 0; k < 32; ++k) {
      float x = sdyn[i * 32 + k];
      float2 wv = __ldg(reinterpret_cast<const float2*>(&p.aff_w0[k * 32 + c]));
      acc0 = fmaf(x, wv.x, acc0);
      acc1 = fmaf(x, wv.y, acc1);
    }
    t1[i * 32 + c]     = tanhf(acc0);
    t1[i * 32 + c + 1] = tanhf(acc1);
  }
  __syncthreads();

  for (int idx = t; idx < 512; idx += 256) {
    int i = idx >> 4, c = (idx & 15) * 2;
    float2 b = __ldg(reinterpret_cast<const float2*>(&p.aff_b1[c]));
    float acc0 = b.x, acc1 = b.y;
    #pragma unroll
    for (int k = 0; k < 32; ++k) {
      float x = t1[i * 32 + k];
      float2 wv = __ldg(reinterpret_cast<const float2*>(&p.aff_w1[k * 32 + c]));
      acc0 = fmaf(x, wv.x, acc0);
      acc1 = fmaf(x, wv.y, acc1);
    }
    t2[i * 32 + c]     = tanhf(acc0) + t1[i * 32 + c];
    t2[i * 32 + c + 1] = tanhf(acc1) + t1[i * 32 + c + 1];
  }
  __syncthreads();

  for (int idx = t; idx < 512; idx += 256) {
    int i = idx >> 4, c = (idx & 15) * 2;
    float2 b = __ldg(reinterpret_cast<const float2*>(&p.aff_b2[c]));
    float acc0 = b.x, acc1 = b.y;
    #pragma unroll
    for (int k = 0; k < 32; ++k) {
      float x = t2[i * 32 + k];
      float2 wv = __ldg(reinterpret_cast<const float2*>(&p.aff_w2[k * 32 + c]));
      acc0 = fmaf(x, wv.x, acc0);
      acc1 = fmaf(x, wv.y, acc1);
    }
    t3[i * 32 + c]     = acc0;
    t3[i * 32 + c + 1] = acc1;
  }
  __syncthreads();

  for (int idx = t; idx < 512; idx += 256) {
    int i = idx >> 4, c = (idx & 15) * 2;
    float2 b = __ldg(reinterpret_cast<const float2*>(&p.out_b0[c]));
    float acc0 = b.x, acc1 = b.y;
    #pragma unroll
    for (int k = 0; k < 32; ++k) {
      float x = t3[i * 32 + k];
      float2 wv = __ldg(reinterpret_cast<const float2*>(&p.out_w0[k * 32 + c]));
      acc0 = fmaf(x, wv.x, acc0);
      acc1 = fmaf(x, wv.y, acc1);
    }
    #pragma unroll
    for (int k = 0; k < 32; ++k) {
      float x = s2[i * 32 + k];
      float2 wv = __ldg(reinterpret_cast<const float2*>(&p.out_w0[(32 + k) * 32 + c]));
      acc0 = fmaf(x, wv.x, acc0);
      acc1 = fmaf(x, wv.y, acc1);
    }
    t1[i * 32 + c]     = tanhf(acc0);
    t1[i * 32 + c + 1] = tanhf(acc1);
  }
  __syncthreads();

  float* og = p.out + (size_t)n * (NOBJ * CL);
  for (int idx = t; idx < 512; idx += 256) {
    int i = idx >> 4, c = (idx & 15) * 2;
    float2 b = __ldg(reinterpret_cast<const float2*>(&p.out_b1[c]));
    float acc0 = b.x + t1[i * 32 + c];
    float acc1 = b.y + t1[i * 32 + c + 1];
    #pragma unroll
    for (int k = 0; k < 32; ++k) {
      float x = t1[i * 32 + k];
      float2 wv = __ldg(reinterpret_cast<const float2*>(&p.out_w1[k * 32 + c]));
      acc0 = fmaf(x, wv.x, acc0);
      acc1 = fmaf(x, wv.y, acc1);
    }
    og[i * 32 + c]     = acc0;
    og[i * 32 + c + 1] = acc1;
  }
}

extern "C" void kernel_launch(void* const* d_in, const int* in_sizes, int n_in,
                              void* d_out, int out_size)
{
  Params p;
  p.s       = (const float*)d_in[0];
  p.enc_w   = (const float*)d_in[1];  p.enc_b   = (const float*)d_in[2];
  p.self_w0 = (const float*)d_in[3];  p.self_b0 = (const float*)d_in[4];
  p.self_w1 = (const float*)d_in[5];  p.self_b1 = (const float*)d_in[6];
  p.rel_w0  = (const float*)d_in[7];  p.rel_b0  = (const float*)d_in[8];
  p.rel_w1  = (const float*)d_in[9];  p.rel_b1  = (const float*)d_in[10];
  p.rel_w2  = (const float*)d_in[11]; p.rel_b2  = (const float*)d_in[12];
  p.att_w0  = (const float*)d_in[13]; p.att_b0  = (const float*)d_in[14];
  p.att_w1  = (const float*)d_in[15]; p.att_b1  = (const float*)d_in[16];
  p.att_w2  = (const float*)d_in[17]; p.att_b2  = (const float*)d_in[18];
  p.aff_w0  = (const float*)d_in[19]; p.aff_b0  = (const float*)d_in[20];
  p.aff_w1  = (const float*)d_in[21]; p.aff_b1  = (const float*)d_in[22];
  p.aff_w2  = (const float*)d_in[23]; p.aff_b2  = (const float*)d_in[24];
  p.out_w0  = (const float*)d_in[25]; p.out_b0  = (const float*)d_in[26];
  p.out_w1  = (const float*)d_in[27]; p.out_b1  = (const float*)d_in[28];
  p.out     = (float*)d_out;

  int N = in_sizes[0] / (NOBJ * (CL / 2));
  dynamics_kernel<<<N, 256>>>(p);
}

// round 14
// speedup vs baseline: 3.6719x; 1.2278x over previous
#include <cuda_runtime.h>
#include <math.h>
#include <stdint.h>

#define CL 32
#define NOBJ 32
#define PADW 68   // padded row stride (floats) — conflict-free without XOR

struct Params {
  const float *s;
  const float *enc_w, *enc_b;
  const float *self_w0, *self_b0, *self_w1, *self_b1;
  const float *rel_w0, *rel_b0, *rel_w1, *rel_b1, *rel_w2, *rel_b2;
  const float *att_w0, *att_b0, *att_w1, *att_b1, *att_w2, *att_b2;
  const float *aff_w0, *aff_b0, *aff_w1, *aff_b1, *aff_w2, *aff_b2;
  const float *out_w0, *out_b0, *out_w1, *out_b1;
  float *out;
};

__device__ __forceinline__ uint32_t tf32_rna(float x) {
  uint32_t r;
  asm("cvt.rna.tf32.f32 %0, %1;" : "=r"(r) : "f"(x));
  return r;
}

// m16n8k8 tf32 MMA: D = A@B + D. A row-major, B col-major. 32-bit operands only.
#define MMA_TF32(c0, c1, c2, c3, a0, a1, a2, a3, b0, b1)                       \
  asm("mma.sync.aligned.m16n8k8.row.col.f32.tf32.tf32.f32 "                    \
      "{%0,%1,%2,%3}, {%4,%5,%6,%7}, {%8,%9}, {%0,%1,%2,%3};"                  \
      : "+f"(c0), "+f"(c1), "+f"(c2), "+f"(c3)                                 \
      : "r"(a0), "r"(a1), "r"(a2), "r"(a3), "r"(b0), "r"(b1))

#define FOR_NT(F) F(0) F(1) F(2) F(3)

__global__ void __launch_bounds__(256) dynamics_kernel(Params p)
{
  // ---- shared (~47.4 KB) ----
  __shared__ __align__(16) float s2[NOBJ * CL];           // 4 KB
  __shared__ __align__(16) float pa[NOBJ * 64];           // 8 KB; tail t1/t2
  __shared__ __align__(16) float ctT[33 * PADW];          // 8.98 KB (row 32 = wd)
  __shared__ __align__(16) uint32_t WhT[32 * PADW];       // 8.7 KB; tail t3 alias
  __shared__ __align__(16) uint32_t WlT[32 * PADW];       // 8.7 KB; sdyn alias
  __shared__ __align__(16) float ssm[NOBJ * CL];          // 4 KB: S matrix
  __shared__ __align__(16) float attv[NOBJ * CL];         // 4 KB: ssrc / att / h1
  __shared__ __align__(16) float miscA[32], miscB[32], miscC[32], avec[32];
  __shared__ float bA2s;

  float* sdyn = reinterpret_cast<float*>(WlT);            // 1024 floats
  float* wdf  = ctT + 32 * PADW;                          // 64 floats

  const int n    = blockIdx.x;
  const int t    = threadIdx.x;
  const int lane = t & 31;
  const int w    = t >> 5;
  const int gid  = lane >> 2;   // groupID
  const int tig  = lane & 3;    // threadID in group

  // ---- stage raw s (overlay in attv) ----
  {
    float* ssrc = attv;
    const float* sp = p.s + (size_t)n * (NOBJ * 16);
    for (int idx = t; idx < NOBJ * 16; idx += 256) ssrc[idx] = sp[idx];
  }
  __syncthreads();

  // ---- s2 = concat(s[:, :2], (s @ enc_w + enc_b)[:, 2:]) ----
  {
    const float* ssrc = attv;
    for (int idx = t; idx < NOBJ * CL; idx += 256) {
      int i = idx >> 5, c = idx & 31;
      float acc = __ldg(&p.enc_b[c]);
      #pragma unroll
      for (int k = 0; k < 16; ++k)
        acc = fmaf(ssrc[i * 16 + k], __ldg(&p.enc_w[k * 32 + c]), acc);
      s2[idx] = (c < 2) ? ssrc[i * 16 + c] : acc;
    }
  }
  __syncthreads();

  // ================= PAIR PHASE (tensor cores, tf32 x2) =================
  #pragma unroll 1
  for (int br = 0; br < 2; ++br) {
    const float* W0  = br ? p.rel_w0 : p.att_w0;
    const float* B0  = br ? p.rel_b0 : p.att_b0;
    const float* W1  = br ? p.rel_w1 : p.att_w1;
    const float* B1s = br ? p.rel_b1 : p.att_b1;

    // ---- stage W1 split hi/lo into padded smem ----
    for (int e = t; e < 2048; e += 256) {
      int k = e >> 5, nn = e & 31;
      float wv = __ldg(&W1[e]);                 // W1[k*32+nn], coalesced
      uint32_t hi = tf32_rna(wv);
      uint32_t lo = tf32_rna(wv - __uint_as_float(hi));
      int a = nn * PADW + k;
      WhT[a] = hi;
      WlT[a] = lo;
    }
    if (t < 64) wdf[t] = __ldg(&W0[64 * 64 + t]);
    else if (t < 96) {
      int c = t - 64;
      miscA[c] = __ldg(&B1s[c]);
      if (!br) miscB[c] = __ldg(&p.att_w2[c]);
      else     miscC[c] = __ldg(&p.rel_b2[c]);
    } else if (t == 96 && !br) {
      bA2s = __ldg(&p.att_b2[0]);
    }

    // ---- projections: pa (bias folded) and ctT (padded) ----
    for (int idx = t; idx < 1024; idx += 256) {
      int io = idx >> 5, k = (idx & 31) * 2;
      float a0 = 0.f, a1 = 0.f, c0 = 0.f, c1 = 0.f;
      #pragma unroll
      for (int cc = 0; cc < 32; ++cc) {
        float sv = s2[io * 32 + cc];
        float2 wa = __ldg(reinterpret_cast<const float2*>(&W0[cc * 64 + k]));
        float2 wc = __ldg(reinterpret_cast<const float2*>(&W0[(32 + cc) * 64 + k]));
        a0 = fmaf(sv, wa.x, a0);
        a1 = fmaf(sv, wa.y, a1);
        c0 = fmaf(sv, wc.x, c0);
        c1 = fmaf(sv, wc.y, c1);
      }
      float2 bv = __ldg(reinterpret_cast<const float2*>(&B0[k]));
      pa[io * 64 + k]     = a0 + bv.x;
      pa[io * 64 + k + 1] = a1 + bv.y;
      ctT[io * PADW + k]     = c0;
      ctT[io * PADW + k + 1] = c1;
    }
    __syncthreads();

    const int n68_0 = (0 * 8 + gid) * PADW;
    const int n68_1 = (1 * 8 + gid) * PADW;
    const int n68_2 = (2 * 8 + gid) * PADW;
    const int n68_3 = (3 * 8 + gid) * PADW;

    #pragma unroll 1
    for (int q = 0; q < 4; ++q) {
      const int i   = w * 4 + q;
      const int i64 = i * 64;
      const int jA = gid, jB = gid + 8, jC = gid + 16, jD = gid + 24;
      const int jA68 = jA * PADW, jB68 = jB * PADW;
      const int jC68 = jC * PADW, jD68 = jD * PADW;

      float pix = s2[i * 32 + 0], piy = s2[i * 32 + 1];
      float dxA = pix - s2[jA * 32 + 0], dyA = piy - s2[jA * 32 + 1];
      float dxB = pix - s2[jB * 32 + 0], dyB = piy - s2[jB * 32 + 1];
      float dxC = pix - s2[jC * 32 + 0], dyC = piy - s2[jC * 32 + 1];
      float dxD = pix - s2[jD * 32 + 0], dyD = piy - s2[jD * 32 + 1];
      float dA = fmaf(dxA, dxA, dyA * dyA);
      float dB = fmaf(dxB, dxB, dyB * dyB);
      float dC = fmaf(dxC, dxC, dyC * dyC);
      float dD = fmaf(dxD, dxD, dyD * dyD);

      float bb0a = miscA[0  + 2 * tig], bb0b = miscA[0  + 2 * tig + 1];
      float bb1a = miscA[8  + 2 * tig], bb1b = miscA[8  + 2 * tig + 1];
      float bb2a = miscA[16 + 2 * tig], bb2b = miscA[16 + 2 * tig + 1];
      float bb3a = miscA[24 + 2 * tig], bb3b = miscA[24 + 2 * tig + 1];

#define DECL_C(nt)                                                             \
      float c0n##nt##_0 = bb##nt##a, c0n##nt##_1 = bb##nt##b,                  \
            c0n##nt##_2 = bb##nt##a, c0n##nt##_3 = bb##nt##b,                  \
            c1n##nt##_0 = bb##nt##a, c1n##nt##_1 = bb##nt##b,                  \
            c1n##nt##_2 = bb##nt##a, c1n##nt##_3 = bb##nt##b;
      FOR_NT(DECL_C)
#undef DECL_C

      #pragma unroll 2
      for (int kt = 0; kt < 8; ++kt) {
        const int k0 = kt * 8 + tig;
        const int k1 = k0 + 4;

        float pa0 = pa[i64 + k0], pa1 = pa[i64 + k1];
        float wk0 = wdf[k0],      wk1 = wdf[k1];

        float vA0 = fmaxf(fmaf(dA, wk0, pa0 + ctT[jA68 + k0]), 0.f);
        float vB0 = fmaxf(fmaf(dB, wk0, pa0 + ctT[jB68 + k0]), 0.f);
        float vC0 = fmaxf(fmaf(dC, wk0, pa0 + ctT[jC68 + k0]), 0.f);
        float vD0 = fmaxf(fmaf(dD, wk0, pa0 + ctT[jD68 + k0]), 0.f);
        float vA1 = fmaxf(fmaf(dA, wk1, pa1 + ctT[jA68 + k1]), 0.f);
        float vB1 = fmaxf(fmaf(dB, wk1, pa1 + ctT[jB68 + k1]), 0.f);
        float vC1 = fmaxf(fmaf(dC, wk1, pa1 + ctT[jC68 + k1]), 0.f);
        float vD1 = fmaxf(fmaf(dD, wk1, pa1 + ctT[jD68 + k1]), 0.f);

        uint32_t hA0 = tf32_rna(vA0), hB0 = tf32_rna(vB0);
        uint32_t hC0 = tf32_rna(vC0), hD0 = tf32_rna(vD0);
        uint32_t hA1 = tf32_rna(vA1), hB1 = tf32_rna(vB1);
        uint32_t hC1 = tf32_rna(vC1), hD1 = tf32_rna(vD1);

#define MMA_NT(nt) {                                                           \
        uint32_t bh0 = WhT[n68_##nt + k0], bh1 = WhT[n68_##nt + k1];           \
        uint32_t bl0 = WlT[n68_##nt + k0], bl1 = WlT[n68_##nt + k1];           \
        MMA_TF32(c0n##nt##_0, c0n##nt##_1, c0n##nt##_2, c0n##nt##_3,           \
                 hA0, hB0, hA1, hB1, bh0, bh1);                                \
        MMA_TF32(c0n##nt##_0, c0n##nt##_1, c0n##nt##_2, c0n##nt##_3,           \
                 hA0, hB0, hA1, hB1, bl0, bl1);                                \
        MMA_TF32(c1n##nt##_0, c1n##nt##_1, c1n##nt##_2, c1n##nt##_3,           \
                 hC0, hD0, hC1, hD1, bh0, bh1);                                \
        MMA_TF32(c1n##nt##_0, c1n##nt##_1, c1n##nt##_2, c1n##nt##_3,           \
                 hC0, hD0, hC1, hD1, bl0, bl1); }
        FOR_NT(MMA_NT)
#undef MMA_NT
      }

      if (!br) {
        // ---- att epilogue: logit = b2 + sum_n relu(C)*w2[n] ----
        float lgA = 0.f, lgB = 0.f, lgC = 0.f, lgD = 0.f;
#define ATT_NT(nt) {                                                           \
        float w2a = miscB[nt * 8 + 2 * tig], w2b = miscB[nt * 8 + 2 * tig + 1];\
        lgA = fmaf(fmaxf(c0n##nt##_0, 0.f), w2a, lgA);                         \
        lgA = fmaf(fmaxf(c0n##nt##_1, 0.f), w2b, lgA);                         \
        lgB = fmaf(fmaxf(c0n##nt##_2, 0.f), w2a, lgB);                         \
        lgB = fmaf(fmaxf(c0n##nt##_3, 0.f), w2b, lgB);                         \
        lgC = fmaf(fmaxf(c1n##nt##_0, 0.f), w2a, lgC);                         \
        lgC = fmaf(fmaxf(c1n##nt##_1, 0.f), w2b, lgC);                         \
        lgD = fmaf(fmaxf(c1n##nt##_2, 0.f), w2a, lgD);                         \
        lgD = fmaf(fmaxf(c1n##nt##_3, 0.f), w2b, lgD); }
        FOR_NT(ATT_NT)
#undef ATT_NT
        lgA += __shfl_xor_sync(0xffffffffu, lgA, 1);
        lgA += __shfl_xor_sync(0xffffffffu, lgA, 2);
        lgB += __shfl_xor_sync(0xffffffffu, lgB, 1);
        lgB += __shfl_xor_sync(0xffffffffu, lgB, 2);
        lgC += __shfl_xor_sync(0xffffffffu, lgC, 1);
        lgC += __shfl_xor_sync(0xffffffffu, lgC, 2);
        lgD += __shfl_xor_sync(0xffffffffu, lgD, 1);
        lgD += __shfl_xor_sync(0xffffffffu, lgD, 2);
        float aA = (jA == i) ? 0.f : expf(bA2s + lgA);
        float aB = (jB == i) ? 0.f : expf(bA2s + lgB);
        float aC = (jC == i) ? 0.f : expf(bA2s + lgC);
        float aD = (jD == i) ? 0.f : expf(bA2s + lgD);
        if (tig == 0) {
          attv[i * 32 + jA] = aA;
          attv[i * 32 + jB] = aB;
          attv[i * 32 + jC] = aC;
          attv[i * 32 + jD] = aD;
        }
      } else {
        // ---- rel epilogue: S[i,col] = sum_j att*relu(C); A[i] = sum_j att ----
        float atA = attv[i * 32 + jA];
        float atB = attv[i * 32 + jB];
        float atC = attv[i * 32 + jC];
        float atD = attv[i * 32 + jD];
#define REL_NT(nt)                                                             \
        float ps##nt##a = fmaf(atA, fmaxf(c0n##nt##_0, 0.f),                   \
                          fmaf(atB, fmaxf(c0n##nt##_2, 0.f),                   \
                          fmaf(atC, fmaxf(c1n##nt##_0, 0.f),                   \
                               atD * fmaxf(c1n##nt##_2, 0.f))));               \
        float ps##nt##b = fmaf(atA, fmaxf(c0n##nt##_1, 0.f),                   \
                          fmaf(atB, fmaxf(c0n##nt##_3, 0.f),                   \
                          fmaf(atC, fmaxf(c1n##nt##_1, 0.f),                   \
                               atD * fmaxf(c1n##nt##_3, 0.f))));
        FOR_NT(REL_NT)
#undef REL_NT
#define RED_NT(nt) {                                                           \
        ps##nt##a += __shfl_xor_sync(0xffffffffu, ps##nt##a, 4);               \
        ps##nt##a += __shfl_xor_sync(0xffffffffu, ps##nt##a, 8);               \
        ps##nt##a += __shfl_xor_sync(0xffffffffu, ps##nt##a, 16);              \
        ps##nt##b += __shfl_xor_sync(0xffffffffu, ps##nt##b, 4);               \
        ps##nt##b += __shfl_xor_sync(0xffffffffu, ps##nt##b, 8);               \
        ps##nt##b += __shfl_xor_sync(0xffffffffu, ps##nt##b, 16); }
        FOR_NT(RED_NT)
#undef RED_NT
        if (gid == 0) {
#define ST_NT(nt) {                                                            \
          ssm[i * 32 + nt * 8 + 2 * tig]     = ps##nt##a;                      \
          ssm[i * 32 + nt * 8 + 2 * tig + 1] = ps##nt##b; }
          FOR_NT(ST_NT)
#undef ST_NT
        }
        float asum = atA + atB + atC + atD;
        asum += __shfl_xor_sync(0xffffffffu, asum, 4);
        asum += __shfl_xor_sync(0xffffffffu, asum, 8);
        asum += __shfl_xor_sync(0xffffffffu, asum, 16);
        if (lane == 0) avec[i] = asum;
      }
    }
    __syncthreads();
  }

  // ---- self branch (after pair; h1 in attv, out to sdyn alias) ----
  for (int idx = t; idx < 512; idx += 256) {
    int i = idx >> 4, c = (idx & 15) * 2;
    float2 b = __ldg(reinterpret_cast<const float2*>(&p.self_b0[c]));
    float acc0 = b.x, acc1 = b.y;
    #pragma unroll
    for (int k = 0; k < 32; ++k) {
      float x = s2[i * 32 + k];
      float2 wv = __ldg(reinterpret_cast<const float2*>(&p.self_w0[k * 32 + c]));
      acc0 = fmaf(x, wv.x, acc0);
      acc1 = fmaf(x, wv.y, acc1);
    }
    attv[i * 32 + c]     = fmaxf(acc0, 0.0f);
    attv[i * 32 + c + 1] = fmaxf(acc1, 0.0f);
  }
  __syncthreads();
  for (int idx = t; idx < 512; idx += 256) {
    int i = idx >> 4, c = (idx & 15) * 2;
    float2 b = __ldg(reinterpret_cast<const float2*>(&p.self_b1[c]));
    float acc0 = b.x + attv[i * 32 + c];
    float acc1 = b.y + attv[i * 32 + c + 1];
    #pragma unroll
    for (int k = 0; k < 32; ++k) {
      float x = attv[i * 32 + k];
      float2 wv = __ldg(reinterpret_cast<const float2*>(&p.self_w1[k * 32 + c]));
      acc0 = fmaf(x, wv.x, acc0);
      acc1 = fmaf(x, wv.y, acc1);
    }
    sdyn[i * 32 + c]     = acc0;
    sdyn[i * 32 + c + 1] = acc1;
  }
  __syncthreads();

  // ---- dyn = self_dyn + S@W2 + A*b2 + S ----
  for (int idx = t; idx < 512; idx += 256) {
    int i = idx >> 4, m = (idx & 15) * 2;
    float acc0 = sdyn[i * 32 + m]     + ssm[i * 32 + m]     + avec[i] * miscC[m];
    float acc1 = sdyn[i * 32 + m + 1] + ssm[i * 32 + m + 1] + avec[i] * miscC[m + 1];
    #pragma unroll
    for (int k = 0; k < 32; ++k) {
      float x = ssm[i * 32 + k];
      float2 wv = __ldg(reinterpret_cast<const float2*>(&p.rel_w2[k * 32 + m]));
      acc0 = fmaf(x, wv.x, acc0);
      acc1 = fmaf(x, wv.y, acc1);
    }
    sdyn[i * 32 + m]     = acc0;
    sdyn[i * 32 + m + 1] = acc1;
  }
  __syncthreads();

  // ---- tail MLP chain ----
  float* t1 = pa;
  float* t2 = pa + 1024;
  float* t3 = reinterpret_cast<float*>(WhT);

  for (int idx = t; idx < 512; idx += 256) {
    int i = idx >> 4, c = (idx & 15) * 2;
    float2 b = __ldg(reinterpret_cast<const float2*>(&p.aff_b0[c]));
    float acc0 = b.x, acc1 = b.y;
    #pragma unroll
    for (int k = 0; k < 32; ++k) {
      float x = sdyn[i * 32 + k];
      float2 wv = __ldg(reinterpret_cast<const float2*>(&p.aff_w0[k * 32 + c]));
      acc0 = fmaf(x, wv.x, acc0);
      acc1 = fmaf(x, wv.y, acc1);
    }
    t1[i * 32 + c]     = tanhf(acc0);
    t1[i * 32 + c + 1] = tanhf(acc1);
  }
  __syncthreads();

  for (int idx = t; idx < 512; idx += 256) {
    int i = idx >> 4, c = (idx & 15) * 2;
    float2 b = __ldg(reinterpret_cast<const float2*>(&p.aff_b1[c]));
    float acc0 = b.x, acc1 = b.y;
    #pragma unroll
    for (int k = 0; k < 32; ++k) {
      float x = t1[i * 32 + k];
      float2 wv = __ldg(reinterpret_cast<const float2*>(&p.aff_w1[k * 32 + c]));
      acc0 = fmaf(x, wv.x, acc0);
      acc1 = fmaf(x, wv.y, acc1);
    }
    t2[i * 32 + c]     = tanhf(acc0) + t1[i * 32 + c];
    t2[i * 32 + c + 1] = tanhf(acc1) + t1[i * 32 + c + 1];
  }
  __syncthreads();

  for (int idx = t; idx < 512; idx += 256) {
    int i = idx >> 4, c = (idx & 15) * 2;
    float2 b = __ldg(reinterpret_cast<const float2*>(&p.aff_b2[c]));
    float acc0 = b.x, acc1 = b.y;
    #pragma unroll
    for (int k = 0; k < 32; ++k) {
      float x = t2[i * 32 + k];
      float2 wv = __ldg(reinterpret_cast<const float2*>(&p.aff_w2[k * 32 + c]));
      acc0 = fmaf(x, wv.x, acc0);
      acc1 = fmaf(x, wv.y, acc1);
    }
    t3[i * 32 + c]     = acc0;
    t3[i * 32 + c + 1] = acc1;
  }
  __syncthreads();

  for (int idx = t; idx < 512; idx += 256) {
    int i = idx >> 4, c = (idx & 15) * 2;
    float2 b = __ldg(reinterpret_cast<const float2*>(&p.out_b0[c]));
    float acc0 = b.x, acc1 = b.y;
    #pragma unroll
    for (int k = 0; k < 32; ++k) {
      float x = t3[i * 32 + k];
      float2 wv = __ldg(reinterpret_cast<const float2*>(&p.out_w0[k * 32 + c]));
      acc0 = fmaf(x, wv.x, acc0);
      acc1 = fmaf(x, wv.y, acc1);
    }
    #pragma unroll
    for (int k = 0; k < 32; ++k) {
      float x = s2[i * 32 + k];
      float2 wv = __ldg(reinterpret_cast<const float2*>(&p.out_w0[(32 + k) * 32 + c]));
      acc0 = fmaf(x, wv.x, acc0);
      acc1 = fmaf(x, wv.y, acc1);
    }
    t1[i * 32 + c]     = tanhf(acc0);
    t1[i * 32 + c + 1] = tanhf(acc1);
  }
  __syncthreads();

  float* og = p.out + (size_t)n * (NOBJ * CL);
  for (int idx = t; idx < 512; idx += 256) {
    int i = idx >> 4, c = (idx & 15) * 2;
    float2 b = __ldg(reinterpret_cast<const float2*>(&p.out_b1[c]));
    float acc0 = b.x + t1[i * 32 + c];
    float acc1 = b.y + t1[i * 32 + c + 1];
    #pragma unroll
    for (int k = 0; k < 32; ++k) {
      float x = t1[i * 32 + k];
      float2 wv = __ldg(reinterpret_cast<const float2*>(&p.out_w1[k * 32 + c]));
      acc0 = fmaf(x, wv.x, acc0);
      acc1 = fmaf(x, wv.y, acc1);
    }
    og[i * 32 + c]     = acc0;
    og[i * 32 + c + 1] = acc1;
  }
}

extern "C" void kernel_launch(void* const* d_in, const int* in_sizes, int n_in,
                              void* d_out, int out_size)
{
  Params p;
  p.s       = (const float*)d_in[0];
  p.enc_w   = (const float*)d_in[1];  p.enc_b   = (const float*)d_in[2];
  p.self_w0 = (const float*)d_in[3];  p.self_b0 = (const float*)d_in[4];
  p.self_w1 = (const float*)d_in[5];  p.self_b1 = (const float*)d_in[6];
  p.rel_w0  = (const float*)d_in[7];  p.rel_b0  = (const float*)d_in[8];
  p.rel_w1  = (const float*)d_in[9];  p.rel_b1  = (const float*)d_in[10];
  p.rel_w2  = (const float*)d_in[11]; p.rel_b2  = (const float*)d_in[12];
  p.att_w0  = (const float*)d_in[13]; p.att_b0  = (const float*)d_in[14];
  p.att_w1  = (const float*)d_in[15]; p.att_b1  = (const float*)d_in[16];
  p.att_w2  = (const float*)d_in[17]; p.att_b2  = (const float*)d_in[18];
  p.aff_w0  = (const float*)d_in[19]; p.aff_b0  = (const float*)d_in[20];
  p.aff_w1  = (const float*)d_in[21]; p.aff_b1  = (const float*)d_in[22];
  p.aff_w2  = (const float*)d_in[23]; p.aff_b2  = (const float*)d_in[24];
  p.out_w0  = (const float*)d_in[25]; p.out_b0  = (const float*)d_in[26];
  p.out_w1  = (const float*)d_in[27]; p.out_b1  = (const float*)d_in[28];
  p.out     = (float*)d_out;

  int N = in_sizes[0] / (NOBJ * (CL / 2));
  dynamics_kernel<<<N, 256>>>(p);
}

// round 15
// speedup vs baseline: 3.8386x; 1.0454x over previous
#include <cuda_runtime.h>
#include <math.h>
#include <stdint.h>

#define CL 32
#define NOBJ 32
#define PADW 68   // padded row stride (floats) — conflict-free without XOR

struct Params {
  const float *s;
  const float *enc_w, *enc_b;
  const float *self_w0, *self_b0, *self_w1, *self_b1;
  const float *rel_w0, *rel_b0, *rel_w1, *rel_b1, *rel_w2, *rel_b2;
  const float *att_w0, *att_b0, *att_w1, *att_b1, *att_w2, *att_b2;
  const float *aff_w0, *aff_b0, *aff_w1, *aff_b1, *aff_w2, *aff_b2;
  const float *out_w0, *out_b0, *out_w1, *out_b1;
  float *out;
};

__device__ __forceinline__ uint32_t tf32_rna(float x) {
  uint32_t r;
  asm("cvt.rna.tf32.f32 %0, %1;" : "=r"(r) : "f"(x));
  return r;
}

// m16n8k8 tf32 MMA: D = A@B + D. A row-major, B col-major. 32-bit operands only.
#define MMA_TF32(c0, c1, c2, c3, a0, a1, a2, a3, b0, b1)                       \
  asm("mma.sync.aligned.m16n8k8.row.col.f32.tf32.tf32.f32 "                    \
      "{%0,%1,%2,%3}, {%4,%5,%6,%7}, {%8,%9}, {%0,%1,%2,%3};"                  \
      : "+f"(c0), "+f"(c1), "+f"(c2), "+f"(c3)                                 \
      : "r"(a0), "r"(a1), "r"(a2), "r"(a3), "r"(b0), "r"(b1))

#define FOR_NT(F) F(0) F(1) F(2) F(3)

__global__ void __launch_bounds__(256, 2) dynamics_kernel(Params p)
{
  // ---- shared (~47.4 KB) ----
  __shared__ __align__(16) float s2[NOBJ * CL];           // 4 KB
  __shared__ __align__(16) float pa[NOBJ * 64];           // 8 KB; tail t1/t2
  __shared__ __align__(16) float ctT[33 * PADW];          // 8.98 KB (row 32 = wd)
  __shared__ __align__(16) uint32_t WhT[32 * PADW];       // 8.7 KB; tail t3 alias
  __shared__ __align__(16) uint32_t WlT[32 * PADW];       // 8.7 KB; sdyn alias
  __shared__ __align__(16) float ssm[NOBJ * CL];          // 4 KB: S matrix
  __shared__ __align__(16) float attv[NOBJ * CL];         // 4 KB: ssrc / att / h1
  __shared__ __align__(16) float miscA[32], miscB[32], miscC[32], avec[32];
  __shared__ float bA2s;

  float* sdyn = reinterpret_cast<float*>(WlT);            // 1024 floats
  float* wdf  = ctT + 32 * PADW;                          // 64 floats

  const int n    = blockIdx.x;
  const int t    = threadIdx.x;
  const int lane = t & 31;
  const int w    = t >> 5;
  const int gid  = lane >> 2;   // groupID
  const int tig  = lane & 3;    // threadID in group

  // ---- stage raw s (overlay in attv) ----
  {
    float* ssrc = attv;
    const float* sp = p.s + (size_t)n * (NOBJ * 16);
    for (int idx = t; idx < NOBJ * 16; idx += 256) ssrc[idx] = sp[idx];
  }
  __syncthreads();

  // ---- s2 = concat(s[:, :2], (s @ enc_w + enc_b)[:, 2:]) ----
  {
    const float* ssrc = attv;
    for (int idx = t; idx < NOBJ * CL; idx += 256) {
      int i = idx >> 5, c = idx & 31;
      float acc = __ldg(&p.enc_b[c]);
      #pragma unroll
      for (int k = 0; k < 16; ++k)
        acc = fmaf(ssrc[i * 16 + k], __ldg(&p.enc_w[k * 32 + c]), acc);
      s2[idx] = (c < 2) ? ssrc[i * 16 + c] : acc;
    }
  }
  __syncthreads();

  // ================= PAIR PHASE (tensor cores, tf32 x2) =================
  #pragma unroll 1
  for (int br = 0; br < 2; ++br) {
    const float* W0  = br ? p.rel_w0 : p.att_w0;
    const float* B0  = br ? p.rel_b0 : p.att_b0;
    const float* W1  = br ? p.rel_w1 : p.att_w1;
    const float* B1s = br ? p.rel_b1 : p.att_b1;

    // ---- stage W1 split hi/lo into padded smem ----
    for (int e = t; e < 2048; e += 256) {
      int k = e >> 5, nn = e & 31;
      float wv = __ldg(&W1[e]);                 // W1[k*32+nn], coalesced
      uint32_t hi = tf32_rna(wv);
      uint32_t lo = tf32_rna(wv - __uint_as_float(hi));
      int a = nn * PADW + k;
      WhT[a] = hi;
      WlT[a] = lo;
    }
    if (t < 64) wdf[t] = __ldg(&W0[64 * 64 + t]);
    else if (t < 96) {
      int c = t - 64;
      miscA[c] = __ldg(&B1s[c]);
      if (!br) miscB[c] = __ldg(&p.att_w2[c]);
      else     miscC[c] = __ldg(&p.rel_b2[c]);
    } else if (t == 96 && !br) {
      bA2s = __ldg(&p.att_b2[0]);
    }

    // ---- projections: pa (bias folded) and ctT (padded) ----
    for (int idx = t; idx < 1024; idx += 256) {
      int io = idx >> 5, k = (idx & 31) * 2;
      float a0 = 0.f, a1 = 0.f, c0 = 0.f, c1 = 0.f;
      #pragma unroll
      for (int cc = 0; cc < 32; ++cc) {
        float sv = s2[io * 32 + cc];
        float2 wa = __ldg(reinterpret_cast<const float2*>(&W0[cc * 64 + k]));
        float2 wc = __ldg(reinterpret_cast<const float2*>(&W0[(32 + cc) * 64 + k]));
        a0 = fmaf(sv, wa.x, a0);
        a1 = fmaf(sv, wa.y, a1);
        c0 = fmaf(sv, wc.x, c0);
        c1 = fmaf(sv, wc.y, c1);
      }
      float2 bv = __ldg(reinterpret_cast<const float2*>(&B0[k]));
      pa[io * 64 + k]     = a0 + bv.x;
      pa[io * 64 + k + 1] = a1 + bv.y;
      ctT[io * PADW + k]     = c0;
      ctT[io * PADW + k + 1] = c1;
    }
    __syncthreads();

    const int n68_0 = (0 * 8 + gid) * PADW;
    const int n68_1 = (1 * 8 + gid) * PADW;
    const int n68_2 = (2 * 8 + gid) * PADW;
    const int n68_3 = (3 * 8 + gid) * PADW;

    #pragma unroll 1
    for (int q = 0; q < 4; ++q) {
      const int i   = w * 4 + q;
      const int i64 = i * 64;
      const int jA = gid, jB = gid + 8, jC = gid + 16, jD = gid + 24;
      const int jA68 = jA * PADW, jB68 = jB * PADW;
      const int jC68 = jC * PADW, jD68 = jD * PADW;

      float pix = s2[i * 32 + 0], piy = s2[i * 32 + 1];
      float dxA = pix - s2[jA * 32 + 0], dyA = piy - s2[jA * 32 + 1];
      float dxB = pix - s2[jB * 32 + 0], dyB = piy - s2[jB * 32 + 1];
      float dxC = pix - s2[jC * 32 + 0], dyC = piy - s2[jC * 32 + 1];
      float dxD = pix - s2[jD * 32 + 0], dyD = piy - s2[jD * 32 + 1];
      float dA = fmaf(dxA, dxA, dyA * dyA);
      float dB = fmaf(dxB, dxB, dyB * dyB);
      float dC = fmaf(dxC, dxC, dyC * dyC);
      float dD = fmaf(dxD, dxD, dyD * dyD);

      float bb0a = miscA[0  + 2 * tig], bb0b = miscA[0  + 2 * tig + 1];
      float bb1a = miscA[8  + 2 * tig], bb1b = miscA[8  + 2 * tig + 1];
      float bb2a = miscA[16 + 2 * tig], bb2b = miscA[16 + 2 * tig + 1];
      float bb3a = miscA[24 + 2 * tig], bb3b = miscA[24 + 2 * tig + 1];

#define DECL_C(nt)                                                             \
      float c0n##nt##_0 = bb##nt##a, c0n##nt##_1 = bb##nt##b,                  \
            c0n##nt##_2 = bb##nt##a, c0n##nt##_3 = bb##nt##b,                  \
            c1n##nt##_0 = bb##nt##a, c1n##nt##_1 = bb##nt##b,                  \
            c1n##nt##_2 = bb##nt##a, c1n##nt##_3 = bb##nt##b;
      FOR_NT(DECL_C)
#undef DECL_C

      #pragma unroll 1
      for (int kt = 0; kt < 8; ++kt) {
        const int k0 = kt * 8 + tig;
        const int k1 = k0 + 4;

        float pa0 = pa[i64 + k0], pa1 = pa[i64 + k1];
        float wk0 = wdf[k0],      wk1 = wdf[k1];

        float vA0 = fmaxf(fmaf(dA, wk0, pa0 + ctT[jA68 + k0]), 0.f);
        float vB0 = fmaxf(fmaf(dB, wk0, pa0 + ctT[jB68 + k0]), 0.f);
        float vC0 = fmaxf(fmaf(dC, wk0, pa0 + ctT[jC68 + k0]), 0.f);
        float vD0 = fmaxf(fmaf(dD, wk0, pa0 + ctT[jD68 + k0]), 0.f);
        float vA1 = fmaxf(fmaf(dA, wk1, pa1 + ctT[jA68 + k1]), 0.f);
        float vB1 = fmaxf(fmaf(dB, wk1, pa1 + ctT[jB68 + k1]), 0.f);
        float vC1 = fmaxf(fmaf(dC, wk1, pa1 + ctT[jC68 + k1]), 0.f);
        float vD1 = fmaxf(fmaf(dD, wk1, pa1 + ctT[jD68 + k1]), 0.f);

        uint32_t hA0 = tf32_rna(vA0), hB0 = tf32_rna(vB0);
        uint32_t hC0 = tf32_rna(vC0), hD0 = tf32_rna(vD0);
        uint32_t hA1 = tf32_rna(vA1), hB1 = tf32_rna(vB1);
        uint32_t hC1 = tf32_rna(vC1), hD1 = tf32_rna(vD1);

#define MMA_NT(nt) {                                                           \
        uint32_t bh0 = WhT[n68_##nt + k0], bh1 = WhT[n68_##nt + k1];           \
        uint32_t bl0 = WlT[n68_##nt + k0], bl1 = WlT[n68_##nt + k1];           \
        MMA_TF32(c0n##nt##_0, c0n##nt##_1, c0n##nt##_2, c0n##nt##_3,           \
                 hA0, hB0, hA1, hB1, bh0, bh1);                                \
        MMA_TF32(c0n##nt##_0, c0n##nt##_1, c0n##nt##_2, c0n##nt##_3,           \
                 hA0, hB0, hA1, hB1, bl0, bl1);                                \
        MMA_TF32(c1n##nt##_0, c1n##nt##_1, c1n##nt##_2, c1n##nt##_3,           \
                 hC0, hD0, hC1, hD1, bh0, bh1);                                \
        MMA_TF32(c1n##nt##_0, c1n##nt##_1, c1n##nt##_2, c1n##nt##_3,           \
                 hC0, hD0, hC1, hD1, bl0, bl1); }
        FOR_NT(MMA_NT)
#undef MMA_NT
      }

      if (!br) {
        // ---- att epilogue: logit = b2 + sum_n relu(C)*w2[n] ----
        float lgA = 0.f, lgB = 0.f, lgC = 0.f, lgD = 0.f;
#define ATT_NT(nt) {                                                           \
        float w2a = miscB[nt * 8 + 2 * tig], w2b = miscB[nt * 8 + 2 * tig + 1];\
        lgA = fmaf(fmaxf(c0n##nt##_0, 0.f), w2a, lgA);                         \
        lgA = fmaf(fmaxf(c0n##nt##_1, 0.f), w2b, lgA);                         \
        lgB = fmaf(fmaxf(c0n##nt##_2, 0.f), w2a, lgB);                         \
        lgB = fmaf(fmaxf(c0n##nt##_3, 0.f), w2b, lgB);                         \
        lgC = fmaf(fmaxf(c1n##nt##_0, 0.f), w2a, lgC);                         \
        lgC = fmaf(fmaxf(c1n##nt##_1, 0.f), w2b, lgC);                         \
        lgD = fmaf(fmaxf(c1n##nt##_2, 0.f), w2a, lgD);                         \
        lgD = fmaf(fmaxf(c1n##nt##_3, 0.f), w2b, lgD); }
        FOR_NT(ATT_NT)
#undef ATT_NT
        lgA += __shfl_xor_sync(0xffffffffu, lgA, 1);
        lgA += __shfl_xor_sync(0xffffffffu, lgA, 2);
        lgB += __shfl_xor_sync(0xffffffffu, lgB, 1);
        lgB += __shfl_xor_sync(0xffffffffu, lgB, 2);
        lgC += __shfl_xor_sync(0xffffffffu, lgC, 1);
        lgC += __shfl_xor_sync(0xffffffffu, lgC, 2);
        lgD += __shfl_xor_sync(0xffffffffu, lgD, 1);
        lgD += __shfl_xor_sync(0xffffffffu, lgD, 2);
        float aA = (jA == i) ? 0.f : expf(bA2s + lgA);
        float aB = (jB == i) ? 0.f : expf(bA2s + lgB);
        float aC = (jC == i) ? 0.f : expf(bA2s + lgC);
        float aD = (jD == i) ? 0.f : expf(bA2s + lgD);
        if (tig == 0) {
          attv[i * 32 + jA] = aA;
          attv[i * 32 + jB] = aB;
          attv[i * 32 + jC] = aC;
          attv[i * 32 + jD] = aD;
        }
      } else {
        // ---- rel epilogue: S[i,col] = sum_j att*relu(C); A[i] = sum_j att ----
        float atA = attv[i * 32 + jA];
        float atB = attv[i * 32 + jB];
        float atC = attv[i * 32 + jC];
        float atD = attv[i * 32 + jD];
#define REL_NT(nt)                                                             \
        float ps##nt##a = fmaf(atA, fmaxf(c0n##nt##_0, 0.f),                   \
                          fmaf(atB, fmaxf(c0n##nt##_2, 0.f),                   \
                          fmaf(atC, fmaxf(c1n##nt##_0, 0.f),                   \
                               atD * fmaxf(c1n##nt##_2, 0.f))));               \
        float ps##nt##b = fmaf(atA, fmaxf(c0n##nt##_1, 0.f),                   \
                          fmaf(atB, fmaxf(c0n##nt##_3, 0.f),                   \
                          fmaf(atC, fmaxf(c1n##nt##_1, 0.f),                   \
                               atD * fmaxf(c1n##nt##_3, 0.f))));
        FOR_NT(REL_NT)
#undef REL_NT
#define RED_NT(nt) {                                                           \
        ps##nt##a += __shfl_xor_sync(0xffffffffu, ps##nt##a, 4);               \
        ps##nt##a += __shfl_xor_sync(0xffffffffu, ps##nt##a, 8);               \
        ps##nt##a += __shfl_xor_sync(0xffffffffu, ps##nt##a, 16);              \
        ps##nt##b += __shfl_xor_sync(0xffffffffu, ps##nt##b, 4);               \
        ps##nt##b += __shfl_xor_sync(0xffffffffu, ps##nt##b, 8);               \
        ps##nt##b += __shfl_xor_sync(0xffffffffu, ps##nt##b, 16); }
        FOR_NT(RED_NT)
#undef RED_NT
        if (gid == 0) {
#define ST_NT(nt) {                                                            \
          ssm[i * 32 + nt * 8 + 2 * tig]     = ps##nt##a;                      \
          ssm[i * 32 + nt * 8 + 2 * tig + 1] = ps##nt##b; }
          FOR_NT(ST_NT)
#undef ST_NT
        }
        float asum = atA + atB + atC + atD;
        asum += __shfl_xor_sync(0xffffffffu, asum, 4);
        asum += __shfl_xor_sync(0xffffffffu, asum, 8);
        asum += __shfl_xor_sync(0xffffffffu, asum, 16);
        if (lane == 0) avec[i] = asum;
      }
    }
    __syncthreads();
  }

  // ---- self branch (after pair; h1 in attv, out to sdyn alias) ----
  for (int idx = t; idx < 512; idx += 256) {
    int i = idx >> 4, c = (idx & 15) * 2;
    float2 b = __ldg(reinterpret_cast<const float2*>(&p.self_b0[c]));
    float acc0 = b.x, acc1 = b.y;
    #pragma unroll
    for (int k = 0; k < 32; ++k) {
      float x = s2[i * 32 + k];
      float2 wv = __ldg(reinterpret_cast<const float2*>(&p.self_w0[k * 32 + c]));
      acc0 = fmaf(x, wv.x, acc0);
      acc1 = fmaf(x, wv.y, acc1);
    }
    attv[i * 32 + c]     = fmaxf(acc0, 0.0f);
    attv[i * 32 + c + 1] = fmaxf(acc1, 0.0f);
  }
  __syncthreads();
  for (int idx = t; idx < 512; idx += 256) {
    int i = idx >> 4, c = (idx & 15) * 2;
    float2 b = __ldg(reinterpret_cast<const float2*>(&p.self_b1[c]));
    float acc0 = b.x + attv[i * 32 + c];
    float acc1 = b.y + attv[i * 32 + c + 1];
    #pragma unroll
    for (int k = 0; k < 32; ++k) {
      float x = attv[i * 32 + k];
      float2 wv = __ldg(reinterpret_cast<const float2*>(&p.self_w1[k * 32 + c]));
      acc0 = fmaf(x, wv.x, acc0);
      acc1 = fmaf(x, wv.y, acc1);
    }
    sdyn[i * 32 + c]     = acc0;
    sdyn[i * 32 + c + 1] = acc1;
  }
  __syncthreads();

  // ---- dyn = self_dyn + S@W2 + A*b2 + S ----
  for (int idx = t; idx < 512; idx += 256) {
    int i = idx >> 4, m = (idx & 15) * 2;
    float acc0 = sdyn[i * 32 + m]     + ssm[i * 32 + m]     + avec[i] * miscC[m];
    float acc1 = sdyn[i * 32 + m + 1] + ssm[i * 32 + m + 1] + avec[i] * miscC[m + 1];
    #pragma unroll
    for (int k = 0; k < 32; ++k) {
      float x = ssm[i * 32 + k];
      float2 wv = __ldg(reinterpret_cast<const float2*>(&p.rel_w2[k * 32 + m]));
      acc0 = fmaf(x, wv.x, acc0);
      acc1 = fmaf(x, wv.y, acc1);
    }
    sdyn[i * 32 + m]     = acc0;
    sdyn[i * 32 + m + 1] = acc1;
  }
  __syncthreads();

  // ---- tail MLP chain ----
  float* t1 = pa;
  float* t2 = pa + 1024;
  float* t3 = reinterpret_cast<float*>(WhT);

  for (int idx = t; idx < 512; idx += 256) {
    int i = idx >> 4, c = (idx & 15) * 2;
    float2 b = __ldg(reinterpret_cast<const float2*>(&p.aff_b0[c]));
    float acc0 = b.x, acc1 = b.y;
    #pragma unroll
    for (int k = 0; k < 32; ++k) {
      float x = sdyn[i * 32 + k];
      float2 wv = __ldg(reinterpret_cast<const float2*>(&p.aff_w0[k * 32 + c]));
      acc0 = fmaf(x, wv.x, acc0);
      acc1 = fmaf(x, wv.y, acc1);
    }
    t1[i * 32 + c]     = tanhf(acc0);
    t1[i * 32 + c + 1] = tanhf(acc1);
  }
  __syncthreads();

  for (int idx = t; idx < 512; idx += 256) {
    int i = idx >> 4, c = (idx & 15) * 2;
    float2 b = __ldg(reinterpret_cast<const float2*>(&p.aff_b1[c]));
    float acc0 = b.x, acc1 = b.y;
    #pragma unroll
    for (int k = 0; k < 32; ++k) {
      float x = t1[i * 32 + k];
      float2 wv = __ldg(reinterpret_cast<const float2*>(&p.aff_w1[k * 32 + c]));
      acc0 = fmaf(x, wv.x, acc0);
      acc1 = fmaf(x, wv.y, acc1);
    }
    t2[i * 32 + c]     = tanhf(acc0) + t1[i * 32 + c];
    t2[i * 32 + c + 1] = tanhf(acc1) + t1[i * 32 + c + 1];
  }
  __syncthreads();

  for (int idx = t; idx < 512; idx += 256) {
    int i = idx >> 4, c = (idx & 15) * 2;
    float2 b = __ldg(reinterpret_cast<const float2*>(&p.aff_b2[c]));
    float acc0 = b.x, acc1 = b.y;
    #pragma unroll
    for (int k = 0; k < 32; ++k) {
      float x = t2[i * 32 + k];
      float2 wv = __ldg(reinterpret_cast<const float2*>(&p.aff_w2[k * 32 + c]));
      acc0 = fmaf(x, wv.x, acc0);
      acc1 = fmaf(x, wv.y, acc1);
    }
    t3[i * 32 + c]     = acc0;
    t3[i * 32 + c + 1] = acc1;
  }
  __syncthreads();

  for (int idx = t; idx < 512; idx += 256) {
    int i = idx >> 4, c = (idx & 15) * 2;
    float2 b = __ldg(reinterpret_cast<const float2*>(&p.out_b0[c]));
    float acc0 = b.x, acc1 = b.y;
    #pragma unroll
    for (int k = 0; k < 32; ++k) {
      float x = t3[i * 32 + k];
      float2 wv = __ldg(reinterpret_cast<const float2*>(&p.out_w0[k * 32 + c]));
      acc0 = fmaf(x, wv.x, acc0);
      acc1 = fmaf(x, wv.y, acc1);
    }
    #pragma unroll
    for (int k = 0; k < 32; ++k) {
      float x = s2[i * 32 + k];
      float2 wv = __ldg(reinterpret_cast<const float2*>(&p.out_w0[(32 + k) * 32 + c]));
      acc0 = fmaf(x, wv.x, acc0);
      acc1 = fmaf(x, wv.y, acc1);
    }
    t1[i * 32 + c]     = tanhf(acc0);
    t1[i * 32 + c + 1] = tanhf(acc1);
  }
  __syncthreads();

  float* og = p.out + (size_t)n * (NOBJ * CL);
  for (int idx = t; idx < 512; idx += 256) {
    int i = idx >> 4, c = (idx & 15) * 2;
    float2 b = __ldg(reinterpret_cast<const float2*>(&p.out_b1[c]));
    float acc0 = b.x + t1[i * 32 + c];
    float acc1 = b.y + t1[i * 32 + c + 1];
    #pragma unroll
    for (int k = 0; k < 32; ++k) {
      float x = t1[i * 32 + k];
      float2 wv = __ldg(reinterpret_cast<const float2*>(&p.out_w1[k * 32 + c]));
      acc0 = fmaf(x, wv.x, acc0);
      acc1 = fmaf(x, wv.y, acc1);
    }
    og[i * 32 + c]     = acc0;
    og[i * 32 + c + 1] = acc1;
  }
}

extern "C" void kernel_launch(void* const* d_in, const int* in_sizes, int n_in,
                              void* d_out, int out_size)
{
  Params p;
  p.s       = (const float*)d_in[0];
  p.enc_w   = (const float*)d_in[1];  p.enc_b   = (const float*)d_in[2];
  p.self_w0 = (const float*)d_in[3];  p.self_b0 = (const float*)d_in[4];
  p.self_w1 = (const float*)d_in[5];  p.self_b1 = (const float*)d_in[6];
  p.rel_w0  = (const float*)d_in[7];  p.rel_b0  = (const float*)d_in[8];
  p.rel_w1  = (const float*)d_in[9];  p.rel_b1  = (const float*)d_in[10];
  p.rel_w2  = (const float*)d_in[11]; p.rel_b2  = (const float*)d_in[12];
  p.att_w0  = (const float*)d_in[13]; p.att_b0  = (const float*)d_in[14];
  p.att_w1  = (const float*)d_in[15]; p.att_b1  = (const float*)d_in[16];
  p.att_w2  = (const float*)d_in[17]; p.att_b2  = (const float*)d_in[18];
  p.aff_w0  = (const float*)d_in[19]; p.aff_b0  = (const float*)d_in[20];
  p.aff_w1  = (const float*)d_in[21]; p.aff_b1  = (const float*)d_in[22];
  p.aff_w2  = (const float*)d_in[23]; p.aff_b2  = (const float*)d_in[24];
  p.out_w0  = (const float*)d_in[25]; p.out_b0  = (const float*)d_in[26];
  p.out_w1  = (const float*)d_in[27]; p.out_b1  = (const float*)d_in[28];
  p.out     = (float*)d_out;

  int N = in_sizes[0] / (NOBJ * (CL / 2));
  dynamics_kernel<<<N, 256>>>(p);
}